// round 3
// baseline (speedup 1.0000x reference)
#include <cuda_runtime.h>
#include <cuda_bf16.h>
#include <cstdint>

// ---------------- Problem constants ----------------
#define TT 4
#define BB 16
#define CC 512
#define HH 16
#define WW 16
#define NN 256            // H*W tokens
#define NHEAD 8
#define DH 64             // head dim
#define HID 2048          // 4*C
#define MROWS (TT*BB*NN)  // 16384
#define BNROWS (BB*NN)    // 4096
#define PLANE (BB*CC*HH*WW) // 2097152 (per-t x plane)

// ---------------- Static device scratch (no cudaMalloc allowed) ----------------
__device__ float          g_xt  [(size_t)MROWS*CC];
__device__ float          g_qkv [(size_t)MROWS*3*CC];
__device__ float          g_ff  [(size_t)MROWS*HID];
__device__ float          g_a   [(size_t)MROWS*CC];
__device__ float          g_tmp [(size_t)MROWS*CC];
__device__ float          g_kv  [(size_t)TT*BB*NHEAD*DH*DH];
__device__ unsigned char  g_s1  [(size_t)TT*PLANE];
__device__ unsigned char  g_q   [(size_t)TT*BB*NHEAD*NN*DH];
__device__ unsigned char  g_k   [(size_t)TT*BB*NHEAD*NN*DH];
__device__ unsigned char  g_v   [(size_t)TT*BB*NHEAD*NN*DH];
__device__ __nv_bfloat16  g_h   [(size_t)MROWS*CC];
__device__ __nv_bfloat16  g_h4  [(size_t)MROWS*HID];
__device__ __nv_bfloat16  g_wq  [(size_t)3*CC*CC];
__device__ __nv_bfloat16  g_wp  [(size_t)CC*CC];
__device__ __nv_bfloat16  g_w1  [(size_t)HID*CC];
__device__ __nv_bfloat16  g_w2  [(size_t)CC*HID];

// ---------------- helpers ----------------
__device__ __forceinline__ float sigmoidf_(float w){ return 1.f/(1.f+expf(-w)); }

__device__ __forceinline__ uint32_t smem_u32(const void* p){
    uint32_t a;
    asm("{ .reg .u64 t; cvta.to.shared.u64 t, %1; cvt.u32.u64 %0, t; }" : "=r"(a) : "l"(p));
    return a;
}

// ---------------- weight -> bf16 ----------------
__global__ void k_cvt_bf16(const float* __restrict__ s, __nv_bfloat16* __restrict__ d, int n){
    int i = blockIdx.x*blockDim.x + threadIdx.x;
    if (i < n) d[i] = __float2bfloat16(s[i]);
}

// ---------------- LIF over T on raw input x -> u8 spikes ----------------
__global__ void k_lif1(const float* __restrict__ x, const float* __restrict__ lw,
                       unsigned char* __restrict__ s1){
    int i = blockIdx.x*blockDim.x + threadIdx.x;
    if (i >= PLANE) return;
    float decay = sigmoidf_(lw[0]);
    float v = 0.f;
#pragma unroll
    for (int t = 0; t < TT; t++){
        v += (x[(size_t)t*PLANE + i] - v)*decay;
        unsigned char s = (v >= 1.f);
        s1[(size_t)t*PLANE + i] = s;
        if (s) v = 0.f;
    }
}

// ---------------- depthwise 3x3 conv on spikes + residual (NCHW layout) ----------------
__global__ void k_conv(const float* __restrict__ x, const unsigned char* __restrict__ s1,
                       const float* __restrict__ cw, const float* __restrict__ cb,
                       float* __restrict__ y){
    int i = blockIdx.x*blockDim.x + threadIdx.x;
    if (i >= TT*PLANE) return;
    int w = i & 15, h = (i>>4) & 15, c = (i>>8) & 511;
    int base = i - (h*16 + w);
    float acc = cb[c];
    const float* wk = cw + c*9;
#pragma unroll
    for (int dy = -1; dy <= 1; dy++){
        int hh = h + dy; if ((unsigned)hh >= 16u) continue;
#pragma unroll
        for (int dx = -1; dx <= 1; dx++){
            int ww = w + dx; if ((unsigned)ww >= 16u) continue;
            acc += wk[(dy+1)*3 + (dx+1)] * (float)s1[base + hh*16 + ww];
        }
    }
    y[i] = x[i] + acc;
}

// ---------------- transpose [tb][C][N] -> [tb][N][C] ----------------
__global__ void k_transpose(const float* __restrict__ y, float* __restrict__ xt){
    __shared__ float tile[32][33];
    int tb = blockIdx.z;
    int c0 = blockIdx.y*32, n0 = blockIdx.x*32;
    int tx = threadIdx.x, ty = threadIdx.y;
    const float* src = y + (size_t)tb*CC*NN;
    float* dst = xt + (size_t)tb*NN*CC;
#pragma unroll
    for (int j = 0; j < 32; j += 8)
        tile[ty+j][tx] = src[(size_t)(c0+ty+j)*NN + n0+tx];
    __syncthreads();
#pragma unroll
    for (int j = 0; j < 32; j += 8)
        dst[(size_t)(n0+ty+j)*CC + c0+tx] = tile[tx][ty+j];
}

// ---------------- (optional residual add) + LayerNorm(C) + LIF over T -> bf16 spikes ----------------
__global__ void __launch_bounds__(256) k_ln_lif(
        float* __restrict__ xt, const float* __restrict__ g, const float* __restrict__ bvec,
        const float* __restrict__ lw, int lwi,
        const float* __restrict__ addsrc, const float* __restrict__ abias,
        __nv_bfloat16* __restrict__ hout){
    int bn  = blockIdx.x;
    int tid = threadIdx.x;
    int c0 = tid, c1 = tid + 256;
    float decay = sigmoidf_(lw[lwi]);
    float g0 = g[c0], g1 = g[c1], b0 = bvec[c0], b1 = bvec[c1];
    float ab0 = 0.f, ab1 = 0.f;
    if (abias){ ab0 = abias[c0]; ab1 = abias[c1]; }
    __shared__ float ssum[256], ssq[256];
    float v0 = 0.f, v1 = 0.f;
    for (int t = 0; t < TT; t++){
        size_t base = ((size_t)t*BNROWS + bn)*CC;
        float x0 = xt[base + c0], x1 = xt[base + c1];
        if (addsrc){
            x0 += addsrc[base + c0] + ab0;
            x1 += addsrc[base + c1] + ab1;
            xt[base + c0] = x0; xt[base + c1] = x1;
        }
        ssum[tid] = x0 + x1; ssq[tid] = x0*x0 + x1*x1;
        __syncthreads();
        for (int o = 128; o > 0; o >>= 1){
            if (tid < o){ ssum[tid] += ssum[tid+o]; ssq[tid] += ssq[tid+o]; }
            __syncthreads();
        }
        float mean = ssum[0]*(1.f/512.f);
        float var  = ssq[0]*(1.f/512.f) - mean*mean;
        __syncthreads();
        float rstd = rsqrtf(var + 1e-5f);
        float y0 = (x0 - mean)*rstd*g0 + b0;
        float y1 = (x1 - mean)*rstd*g1 + b1;
        v0 += (y0 - v0)*decay; v1 += (y1 - v1)*decay;
        float s0 = (v0 >= 1.f) ? 1.f : 0.f;
        float s1v = (v1 >= 1.f) ? 1.f : 0.f;
        hout[base + c0] = __float2bfloat16(s0);
        hout[base + c1] = __float2bfloat16(s1v);
        if (s0 > 0.f) v0 = 0.f;
        if (s1v > 0.f) v1 = 0.f;
    }
}

// ---------------- mma.sync bf16 GEMM: C[M,N] = A[M,K] @ W[N,K]^T (fp32 accum) ----------------
// 128x128 CTA tile, 8 warps (4x2), warp tile 32x64, BK=32, 3-stage cp.async ring.
#define BM 128
#define BN 128
#define BK 32
#define STG 3
#define APAD 40                      // smem row stride in elems (80 B)
#define STAGE_BYTES (2*(BM*APAD*2)) // A(10240) + B(10240) = 20480
#define GEMM_DSMEM (STG*STAGE_BYTES)

__global__ void __launch_bounds__(256, 2) k_gemm_mma(
        const __nv_bfloat16* __restrict__ A, const __nv_bfloat16* __restrict__ W,
        float* __restrict__ C, int M, int N, int K){
    extern __shared__ char dsm[];
    const int tid  = threadIdx.x;
    const int lane = tid & 31, warp = tid >> 5;
    const int wm = warp >> 1, wn = warp & 1;          // 4 x 2 warps
    const int bm = blockIdx.y*BM, bn = blockIdx.x*BN;
    const uint32_t sbase = smem_u32(dsm);
    const int nk = K >> 5;

    float acc[2][8][4];
#pragma unroll
    for (int i = 0; i < 2; i++)
#pragma unroll
        for (int j = 0; j < 8; j++)
#pragma unroll
            for (int r = 0; r < 4; r++) acc[i][j][r] = 0.f;

    auto load_stage = [&](int j){
        int s = j % STG;
        uint32_t sa = sbase + s*STAGE_BYTES;
        uint32_t sb = sa + (BM*APAD*2);
        int k0 = j*BK;
#pragma unroll
        for (int i = 0; i < 2; i++){
            int ch  = i*256 + tid;             // 0..511 16B chunks
            int row = ch >> 2, col = (ch & 3)*8;
            const char* ga = (const char*)(A + (size_t)(bm+row)*K + k0 + col);
            const char* gb = (const char*)(W + (size_t)(bn+row)*K + k0 + col);
            uint32_t da = sa + (uint32_t)(row*(APAD*2) + col*2);
            uint32_t db = sb + (uint32_t)(row*(APAD*2) + col*2);
            asm volatile("cp.async.cg.shared.global [%0], [%1], 16;" :: "r"(da), "l"(ga));
            asm volatile("cp.async.cg.shared.global [%0], [%1], 16;" :: "r"(db), "l"(gb));
        }
        asm volatile("cp.async.commit_group;");
    };

    load_stage(0);
    if (nk > 1) load_stage(1); else asm volatile("cp.async.commit_group;");

    for (int j = 0; j < nk; j++){
        asm volatile("cp.async.wait_group 1;");
        __syncthreads();
        int s = j % STG;
        uint32_t abase = sbase + s*STAGE_BYTES;
        uint32_t bbase = abase + (BM*APAD*2);
#pragma unroll
        for (int ks = 0; ks < BK; ks += 16){
            uint32_t a[2][4], b[4][4];
            // A fragments: two m16k16 tiles
#pragma unroll
            for (int mt = 0; mt < 2; mt++){
                int row = wm*32 + mt*16 + (lane & 15);
                int col = ks + ((lane >> 4) << 3);
                uint32_t ad = abase + (uint32_t)(row*(APAD*2) + col*2);
                asm volatile("ldmatrix.sync.aligned.m8n8.x4.shared.b16 {%0,%1,%2,%3}, [%4];"
                             : "=r"(a[mt][0]), "=r"(a[mt][1]), "=r"(a[mt][2]), "=r"(a[mt][3])
                             : "r"(ad));
            }
            // B fragments: four n16k16 tiles (covering 64 cols)
#pragma unroll
            for (int ng = 0; ng < 4; ng++){
                int n = wn*64 + ng*16 + (lane & 7) + (((lane >> 4) & 1) << 3);
                int k = ks + (((lane >> 3) & 1) << 3);
                uint32_t bd = bbase + (uint32_t)(n*(APAD*2) + k*2);
                asm volatile("ldmatrix.sync.aligned.m8n8.x4.shared.b16 {%0,%1,%2,%3}, [%4];"
                             : "=r"(b[ng][0]), "=r"(b[ng][1]), "=r"(b[ng][2]), "=r"(b[ng][3])
                             : "r"(bd));
            }
#pragma unroll
            for (int mt = 0; mt < 2; mt++)
#pragma unroll
                for (int nf = 0; nf < 8; nf++){
                    uint32_t b0 = b[nf >> 1][(nf & 1)*2];
                    uint32_t b1 = b[nf >> 1][(nf & 1)*2 + 1];
                    asm volatile(
                        "mma.sync.aligned.m16n8k16.row.col.f32.bf16.bf16.f32 "
                        "{%0,%1,%2,%3}, {%4,%5,%6,%7}, {%8,%9}, {%0,%1,%2,%3};"
                        : "+f"(acc[mt][nf][0]), "+f"(acc[mt][nf][1]),
                          "+f"(acc[mt][nf][2]), "+f"(acc[mt][nf][3])
                        : "r"(a[mt][0]), "r"(a[mt][1]), "r"(a[mt][2]), "r"(a[mt][3]),
                          "r"(b0), "r"(b1));
                }
        }
        if (j + 2 < nk) load_stage(j + 2);
        else            asm volatile("cp.async.commit_group;");
        __syncthreads();
    }

    // epilogue
#pragma unroll
    for (int mt = 0; mt < 2; mt++){
        int r0 = bm + wm*32 + mt*16 + (lane >> 2);
#pragma unroll
        for (int nf = 0; nf < 8; nf++){
            int c = bn + wn*64 + nf*8 + (lane & 3)*2;
            *(float2*)&C[(size_t)r0*N + c]     = make_float2(acc[mt][nf][0], acc[mt][nf][1]);
            *(float2*)&C[(size_t)(r0+8)*N + c] = make_float2(acc[mt][nf][2], acc[mt][nf][3]);
        }
    }
}

// ---------------- LIF over T on qkv -> q,k,v u8 spikes [t,b,h,n,d] ----------------
__global__ void k_lif_qkv(const float* __restrict__ qkv, const float* __restrict__ lw,
                          unsigned char* __restrict__ q, unsigned char* __restrict__ k,
                          unsigned char* __restrict__ vv){
    int idx = blockIdx.x*blockDim.x + threadIdx.x;
    if (idx >= BNROWS*3*CC) return;
    int j = idx % (3*CC); int bn = idx / (3*CC);
    int i = j / CC; int jj = j - i*CC; int hh = jj >> 6; int dd = jj & 63;
    float decay = sigmoidf_(lw[2 + i]);
    unsigned char* outp = (i == 0) ? q : (i == 1) ? k : vv;
    int b = bn >> 8, n = bn & 255;
    float v = 0.f;
#pragma unroll
    for (int t = 0; t < TT; t++){
        float val = qkv[((size_t)t*BNROWS + bn)*(3*CC) + j];
        v += (val - v)*decay;
        unsigned char s = (v >= 1.f);
        outp[((((size_t)t*BB + b)*NHEAD + hh)*NN + n)*DH + dd] = s;
        if (s) v = 0.f;
    }
}

// ---------------- kv = k^T v via ballot-packed popc (exact int) ----------------
__global__ void __launch_bounds__(256) k_kv(const unsigned char* __restrict__ kk,
                                            const unsigned char* __restrict__ vv,
                                            float* __restrict__ kvout){
    __shared__ unsigned int kb[DH][8], vb[DH][8];
    int tbh = blockIdx.x;
    int tid = threadIdx.x, warp = tid >> 5, lane = tid & 31;
    size_t base = (size_t)tbh*NN*DH;
    for (int w = warp; w < 1024; w += 8){
        int op = w >> 9;
        int r = w & 511; int d = r >> 3; int wg = r & 7;
        const unsigned char* src = op ? vv : kk;
        unsigned char val = src[base + (size_t)(wg*32 + lane)*DH + d];
        unsigned int m = __ballot_sync(0xffffffffu, val != 0);
        if (lane == 0) (op ? vb : kb)[d][wg] = m;
    }
    __syncthreads();
    for (int o = tid; o < DH*DH; o += 256){
        int d = o >> 6, e = o & 63;
        int c = 0;
#pragma unroll
        for (int w = 0; w < 8; w++) c += __popc(kb[d][w] & vb[e][w]);
        kvout[(size_t)tbh*DH*DH + o] = (float)c;
    }
}

// ---------------- a = (q @ kv) * scale, written as [t,b,n,C] ----------------
__global__ void __launch_bounds__(256) k_attn_a(const unsigned char* __restrict__ q,
                                                const float* __restrict__ kvin,
                                                float* __restrict__ a){
    __shared__ float skv[DH][DH];
    __shared__ unsigned int sq[NN][2];
    int tbh = blockIdx.x;
    int tid = threadIdx.x, warp = tid >> 5, lane = tid & 31;
    size_t qbase = (size_t)tbh*NN*DH;
    for (int o = tid; o < DH*DH; o += 256)
        skv[o >> 6][o & 63] = kvin[(size_t)tbh*DH*DH + o];
    for (int w = warp; w < 512; w += 8){
        int n = w >> 1, gidx = w & 1;
        unsigned char val = q[qbase + (size_t)n*DH + gidx*32 + lane];
        unsigned int m = __ballot_sync(0xffffffffu, val != 0);
        if (lane == 0) sq[n][gidx] = m;
    }
    __syncthreads();
    int hh = tbh & 7; int tb = tbh >> 3;
    int e = tid & 63, n0 = tid >> 6;
    for (int n = n0; n < NN; n += 4){
        unsigned int m0 = sq[n][0], m1 = sq[n][1];
        float acc = 0.f;
#pragma unroll
        for (int d = 0; d < 32; d++) if (m0 & (1u << d)) acc += skv[d][e];
#pragma unroll
        for (int d = 0; d < 32; d++) if (m1 & (1u << d)) acc += skv[d + 32][e];
        a[((size_t)tb*NN + n)*CC + hh*DH + e] = acc * 0.125f;
    }
}

// ---------------- generic LIF over T on fp32 [T,R] (+optional per-col bias) -> bf16 spikes ----------------
__global__ void k_lif_elem(const float* __restrict__ in, const float* __restrict__ bias, int nc,
                           const float* __restrict__ lw, int lwi,
                           __nv_bfloat16* __restrict__ out, int R){
    int i = blockIdx.x*blockDim.x + threadIdx.x;
    if (i >= R) return;
    float decay = sigmoidf_(lw[lwi]);
    float bv = bias ? bias[i % nc] : 0.f;
    float v = 0.f;
#pragma unroll
    for (int t = 0; t < TT; t++){
        float val = in[(size_t)t*R + i] + bv;
        v += (val - v)*decay;
        float s = (v >= 1.f) ? 1.f : 0.f;
        out[(size_t)t*R + i] = __float2bfloat16(s);
        if (s > 0.f) v = 0.f;
    }
}

// ---------------- final: out[t,b,c,h,w] = xt + fc2_out + fc2_b (transposed) ----------------
__global__ void k_out(const float* __restrict__ xt, const float* __restrict__ tmp,
                      const float* __restrict__ fb, float* __restrict__ out){
    __shared__ float tile[32][33];
    int tb = blockIdx.z; int n0 = blockIdx.x*32, c0 = blockIdx.y*32;
    int tx = threadIdx.x, ty = threadIdx.y;
    size_t ib = (size_t)tb*NN*CC;
    float bb = fb[c0 + tx];
#pragma unroll
    for (int j = 0; j < 32; j += 8){
        size_t idx = ib + (size_t)(n0 + ty + j)*CC + c0 + tx;
        tile[ty + j][tx] = xt[idx] + tmp[idx] + bb;
    }
    __syncthreads();
    size_t ob = (size_t)tb*CC*NN;
#pragma unroll
    for (int j = 0; j < 32; j += 8)
        out[ob + (size_t)(c0 + ty + j)*NN + n0 + tx] = tile[tx][ty + j];
}

// ---------------- launch ----------------
extern "C" void kernel_launch(void* const* d_in, const int* in_sizes, int n_in,
                              void* d_out, int out_size){
    const float* x      = (const float*)d_in[0];
    const float* conv_w = (const float*)d_in[1];
    const float* conv_b = (const float*)d_in[2];
    const float* ln1_g  = (const float*)d_in[3];
    const float* ln1_b  = (const float*)d_in[4];
    const float* qkv_w  = (const float*)d_in[5];
    const float* proj_w = (const float*)d_in[6];
    const float* proj_b = (const float*)d_in[7];
    const float* ln2_g  = (const float*)d_in[8];
    const float* ln2_b  = (const float*)d_in[9];
    const float* fc1_w  = (const float*)d_in[10];
    const float* fc1_b  = (const float*)d_in[11];
    const float* fc2_w  = (const float*)d_in[12];
    const float* fc2_b  = (const float*)d_in[13];
    const float* lif_w  = (const float*)d_in[14];
    float* out = (float*)d_out;

    void *p_xt, *p_qkv, *p_ff, *p_a, *p_tmp, *p_kv, *p_s1, *p_q, *p_k, *p_v,
         *p_h, *p_h4, *p_wq, *p_wp, *p_w1, *p_w2;
    cudaGetSymbolAddress(&p_xt,  g_xt);
    cudaGetSymbolAddress(&p_qkv, g_qkv);
    cudaGetSymbolAddress(&p_ff,  g_ff);
    cudaGetSymbolAddress(&p_a,   g_a);
    cudaGetSymbolAddress(&p_tmp, g_tmp);
    cudaGetSymbolAddress(&p_kv,  g_kv);
    cudaGetSymbolAddress(&p_s1,  g_s1);
    cudaGetSymbolAddress(&p_q,   g_q);
    cudaGetSymbolAddress(&p_k,   g_k);
    cudaGetSymbolAddress(&p_v,   g_v);
    cudaGetSymbolAddress(&p_h,   g_h);
    cudaGetSymbolAddress(&p_h4,  g_h4);
    cudaGetSymbolAddress(&p_wq,  g_wq);
    cudaGetSymbolAddress(&p_wp,  g_wp);
    cudaGetSymbolAddress(&p_w1,  g_w1);
    cudaGetSymbolAddress(&p_w2,  g_w2);

    float* xt   = (float*)p_xt;
    float* qkv  = (float*)p_qkv;
    float* ff   = (float*)p_ff;
    float* av   = (float*)p_a;
    float* tmp  = (float*)p_tmp;
    float* kvb  = (float*)p_kv;
    unsigned char* s1 = (unsigned char*)p_s1;
    unsigned char* qs = (unsigned char*)p_q;
    unsigned char* ks = (unsigned char*)p_k;
    unsigned char* vs = (unsigned char*)p_v;
    __nv_bfloat16* h  = (__nv_bfloat16*)p_h;
    __nv_bfloat16* h4 = (__nv_bfloat16*)p_h4;
    __nv_bfloat16* wq = (__nv_bfloat16*)p_wq;
    __nv_bfloat16* wp = (__nv_bfloat16*)p_wp;
    __nv_bfloat16* w1 = (__nv_bfloat16*)p_w1;
    __nv_bfloat16* w2 = (__nv_bfloat16*)p_w2;

    cudaFuncSetAttribute(k_gemm_mma, cudaFuncAttributeMaxDynamicSharedMemorySize, GEMM_DSMEM);

    // weight conversion to bf16
    k_cvt_bf16<<<(3*CC*CC + 255)/256, 256>>>(qkv_w, wq, 3*CC*CC);
    k_cvt_bf16<<<(CC*CC   + 255)/256, 256>>>(proj_w, wp, CC*CC);
    k_cvt_bf16<<<(HID*CC  + 255)/256, 256>>>(fc1_w, w1, HID*CC);
    k_cvt_bf16<<<(CC*HID  + 255)/256, 256>>>(fc2_w, w2, CC*HID);

    // 1) LIF on x
    k_lif1<<<PLANE/256, 256>>>(x, lif_w, s1);
    // 2) depthwise conv + residual (NCHW), y stored in g_ff scratch
    k_conv<<<(TT*PLANE)/256, 256>>>(x, s1, conv_w, conv_b, ff);
    // 3) transpose -> xt [t,b,n,c]
    k_transpose<<<dim3(NN/32, CC/32, TT*BB), dim3(32,8)>>>(ff, xt);
    // 4) LN1 + LIF -> h1
    k_ln_lif<<<BNROWS, 256>>>(xt, ln1_g, ln1_b, lif_w, 1, nullptr, nullptr, h);
    // 5) QKV GEMM
    k_gemm_mma<<<dim3(3*CC/BN, MROWS/BM), 256, GEMM_DSMEM>>>(h, wq, qkv, MROWS, 3*CC, CC);
    // 6) LIF on qkv -> q,k,v spikes
    k_lif_qkv<<<(BNROWS*3*CC)/256, 256>>>(qkv, lif_w, qs, ks, vs);
    // 7) kv = k^T v (popc)
    k_kv<<<TT*BB*NHEAD, 256>>>(ks, vs, kvb);
    // 8) a = q @ kv * scale
    k_attn_a<<<TT*BB*NHEAD, 256>>>(qs, kvb, av);
    // 9) LIF on a -> spikes (reuse h)
    k_lif_elem<<<(BNROWS*CC)/256, 256>>>(av, nullptr, 1, lif_w, 5, h, BNROWS*CC);
    // 10) proj GEMM -> tmp
    k_gemm_mma<<<dim3(CC/BN, MROWS/BM), 256, GEMM_DSMEM>>>(h, wp, tmp, MROWS, CC, CC);
    // 11) xt += tmp + proj_b; LN2 + LIF -> h3
    k_ln_lif<<<BNROWS, 256>>>(xt, ln2_g, ln2_b, lif_w, 6, tmp, proj_b, h);
    // 12) FC1 GEMM -> ff
    k_gemm_mma<<<dim3(HID/BN, MROWS/BM), 256, GEMM_DSMEM>>>(h, w1, ff, MROWS, HID, CC);
    // 13) LIF on ff (+fc1_b) -> h4
    k_lif_elem<<<(BNROWS*HID)/256, 256>>>(ff, fc1_b, HID, lif_w, 7, h4, BNROWS*HID);
    // 14) FC2 GEMM -> tmp
    k_gemm_mma<<<dim3(CC/BN, MROWS/BM), 256, GEMM_DSMEM>>>(h4, w2, tmp, MROWS, CC, HID);
    // 15) out = transpose(xt + tmp + fc2_b)
    k_out<<<dim3(NN/32, CC/32, TT*BB), dim3(32,8)>>>(xt, tmp, fc2_b, out);
}

// round 4
// speedup vs baseline: 1.8765x; 1.8765x over previous
#include <cuda_runtime.h>
#include <cuda_bf16.h>
#include <cstdint>

// ---------------- Problem constants ----------------
#define TT 4
#define BB 16
#define CC 512
#define NN 256            // H*W tokens
#define NHEAD 8
#define DH 64
#define HID 2048
#define MROWS (TT*BB*NN)  // 16384
#define BNROWS (BB*NN)    // 4096
#define PLANE (BB*CC*NN)  // 2097152

// Row ordering for all token-major tensors: r = bn*4 + t  (bn = b*256+n)

// ---------------- Static device scratch ----------------
__device__ float          g_xt [(size_t)MROWS*CC];       // tokens [bn*4+t][C]
__device__ float          g_y  [(size_t)TT*PLANE];       // conv out (NCHW)
__device__ float          g_kv [(size_t)TT*BB*NHEAD*DH*DH];
__device__ unsigned char  g_s1 [(size_t)TT*PLANE];
__device__ __nv_bfloat16  g_h  [(size_t)MROWS*CC];       // spike GEMM-LHS
__device__ __nv_bfloat16  g_h4 [(size_t)MROWS*HID];
__device__ uint32_t       g_qm [(size_t)TT*BB*NHEAD*NN*2];
__device__ uint32_t       g_km [(size_t)TT*BB*NHEAD*NN*2];
__device__ uint32_t       g_vm [(size_t)TT*BB*NHEAD*NN*2];
__device__ __nv_bfloat16  g_wq [(size_t)3*CC*CC];
__device__ __nv_bfloat16  g_wp [(size_t)CC*CC];
__device__ __nv_bfloat16  g_w1 [(size_t)HID*CC];
__device__ __nv_bfloat16  g_w2 [(size_t)CC*HID];

__device__ __forceinline__ float sigmoidf_(float w){ return 1.f/(1.f+expf(-w)); }
__device__ __forceinline__ uint32_t smem_u32(const void* p){
    uint32_t a;
    asm("{ .reg .u64 t; cvta.to.shared.u64 t, %1; cvt.u32.u64 %0, t; }" : "=r"(a) : "l"(p));
    return a;
}
__device__ __forceinline__ uint32_t bf01(bool s){ return s ? 0x3F80u : 0u; }

// ---------------- all weights -> bf16, one kernel, float4 ----------------
__global__ void k_cvt_all(const float* __restrict__ a0, const float* __restrict__ a1,
                          const float* __restrict__ a2, const float* __restrict__ a3,
                          __nv_bfloat16* __restrict__ d0, __nv_bfloat16* __restrict__ d1,
                          __nv_bfloat16* __restrict__ d2, __nv_bfloat16* __restrict__ d3){
    int i = blockIdx.x*blockDim.x + threadIdx.x;   // float4 index
    const int n0 = 196608, n1 = 65536, n2 = 262144, n3 = 262144; // /4 counts
    const float* s; __nv_bfloat16* d; int off;
    if      (i < n0){            s=a0; d=d0; off=i; }
    else if (i < n0+n1){         s=a1; d=d1; off=i-n0; }
    else if (i < n0+n1+n2){      s=a2; d=d2; off=i-n0-n1; }
    else if (i < n0+n1+n2+n3){   s=a3; d=d3; off=i-n0-n1-n2; }
    else return;
    float4 v = ((const float4*)s)[off];
    uint32_t lo = (uint32_t)(__bfloat16_as_ushort(__float2bfloat16(v.x)))
                | ((uint32_t)__bfloat16_as_ushort(__float2bfloat16(v.y)) << 16);
    uint32_t hi = (uint32_t)(__bfloat16_as_ushort(__float2bfloat16(v.z)))
                | ((uint32_t)__bfloat16_as_ushort(__float2bfloat16(v.w)) << 16);
    ((uint2*)d)[off] = make_uint2(lo, hi);
}

// ---------------- LIF on x -> u8 spikes (float4, uchar4) ----------------
__global__ void k_lif1(const float* __restrict__ x, const float* __restrict__ lw,
                       uint32_t* __restrict__ s1){
    int i = blockIdx.x*blockDim.x + threadIdx.x;   // < PLANE/4
    float decay = sigmoidf_(lw[0]);
    const float4* xp = (const float4*)x;
    float4 a0 = xp[i], a1 = xp[i + PLANE/4], a2 = xp[i + 2*(PLANE/4)], a3 = xp[i + 3*(PLANE/4)];
    float vx=0,vy=0,vz=0,vw=0;
    uint32_t o[4]; const float4 av[4] = {a0,a1,a2,a3};
#pragma unroll
    for (int t = 0; t < 4; t++){
        float4 a = av[t];
        vx += (a.x - vx)*decay; vy += (a.y - vy)*decay;
        vz += (a.z - vz)*decay; vw += (a.w - vw)*decay;
        uint32_t sx = vx>=1.f, sy = vy>=1.f, sz = vz>=1.f, sw2 = vw>=1.f;
        o[t] = sx | (sy<<8) | (sz<<16) | (sw2<<24);
        if (sx) vx = 0.f; if (sy) vy = 0.f; if (sz) vz = 0.f; if (sw2) vw = 0.f;
    }
#pragma unroll
    for (int t = 0; t < 4; t++) s1[i + t*(PLANE/4)] = o[t];
}

// ---------------- depthwise 3x3 conv + residual, one thread = one (tb,c,h) row ----------------
__global__ void k_conv(const float* __restrict__ x, const unsigned char* __restrict__ s1,
                       const float* __restrict__ cw, const float* __restrict__ cb,
                       float* __restrict__ y){
    int u = blockIdx.x*blockDim.x + threadIdx.x;   // < TT*PLANE/16
    int h = u & 15, c = (u >> 4) & 511;
    size_t p0 = ((size_t)(u >> 13)*512 + c)*256;   // (tb,c) plane base
    union { uint4 v; unsigned char b[16]; } r[3];
#pragma unroll
    for (int dy = 0; dy < 3; dy++){
        int hh = h + dy - 1;
        if ((unsigned)hh < 16u) r[dy].v = *(const uint4*)(s1 + p0 + hh*16);
        else r[dy].v = make_uint4(0,0,0,0);
    }
    float wk[9];
#pragma unroll
    for (int j = 0; j < 9; j++) wk[j] = cw[c*9 + j];
    float bias = cb[c];
    float o[16];
#pragma unroll
    for (int w = 0; w < 16; w++){
        float acc = bias;
#pragma unroll
        for (int dy = 0; dy < 3; dy++)
#pragma unroll
            for (int dx = 0; dx < 3; dx++){
                int ww = w + dx - 1;
                if (ww >= 0 && ww < 16) acc += wk[dy*3+dx] * (float)r[dy].b[ww];
            }
        o[w] = acc;
    }
    const float4* xr = (const float4*)(x + p0 + h*16);
    float4* yr = (float4*)(y + p0 + h*16);
#pragma unroll
    for (int q = 0; q < 4; q++){
        float4 xv = xr[q];
        yr[q] = make_float4(xv.x + o[q*4], xv.y + o[q*4+1], xv.z + o[q*4+2], xv.w + o[q*4+3]);
    }
}

// ---------------- transpose [tb][C][N] -> xt rows (bn*4+t), 64x64 float4 tiles ----------------
__global__ void __launch_bounds__(256) k_tr(const float* __restrict__ y, float* __restrict__ xt){
    __shared__ float s[64][65];
    int bz = blockIdx.z;                 // t*16+b
    int t = bz >> 4, b = bz & 15;
    int n0 = blockIdx.x*64, c0 = blockIdx.y*64;
    int tid = threadIdx.x;
    const float* src = y + (size_t)bz*512*256;
#pragma unroll
    for (int it = 0; it < 4; it++){
        int cr = it*16 + (tid >> 4), ng = (tid & 15)*4;
        float4 f = *(const float4*)&src[(size_t)(c0+cr)*256 + n0 + ng];
        s[cr][ng+0] = f.x; s[cr][ng+1] = f.y; s[cr][ng+2] = f.z; s[cr][ng+3] = f.w;
    }
    __syncthreads();
#pragma unroll
    for (int it = 0; it < 4; it++){
        int nr = it*16 + (tid >> 4), cg = (tid & 15)*4;
        size_t row = (size_t)(b*256 + n0 + nr)*4 + t;
        float4 f = make_float4(s[cg][nr], s[cg+1][nr], s[cg+2][nr], s[cg+3][nr]);
        *(float4*)&xt[row*512 + c0 + cg] = f;
    }
}

// ---------------- LayerNorm(C) + LIF over T -> bf16 spikes (rows bn*4+t) ----------------
__global__ void __launch_bounds__(128) k_ln_lif(
        const float* __restrict__ xt, const float* __restrict__ g, const float* __restrict__ bv,
        const float* __restrict__ lw, int lwi, __nv_bfloat16* __restrict__ h){
    int bn = blockIdx.x, tid = threadIdx.x;
    int lane = tid & 31, w = tid >> 5;
    __shared__ float sw_[4][4], sq_[4][4];
    float decay = sigmoidf_(lw[lwi]);
    float4 gg = *(const float4*)&g[tid*4];
    float4 bb = *(const float4*)&bv[tid*4];
    float v0=0,v1=0,v2=0,v3=0;
#pragma unroll
    for (int t = 0; t < 4; t++){
        size_t r = (size_t)bn*4 + t;
        float4 xv = *(const float4*)&xt[r*512 + tid*4];
        float s = xv.x+xv.y+xv.z+xv.w;
        float q = xv.x*xv.x+xv.y*xv.y+xv.z*xv.z+xv.w*xv.w;
#pragma unroll
        for (int o = 16; o > 0; o >>= 1){
            s += __shfl_xor_sync(0xffffffffu, s, o);
            q += __shfl_xor_sync(0xffffffffu, q, o);
        }
        if (lane == 0){ sw_[t][w] = s; sq_[t][w] = q; }
        __syncthreads();
        float ts = sw_[t][0]+sw_[t][1]+sw_[t][2]+sw_[t][3];
        float tq = sq_[t][0]+sq_[t][1]+sq_[t][2]+sq_[t][3];
        float mean = ts*(1.f/512.f);
        float var  = tq*(1.f/512.f) - mean*mean;
        float rstd = rsqrtf(var + 1e-5f);
        float y0 = (xv.x-mean)*rstd*gg.x + bb.x;
        float y1 = (xv.y-mean)*rstd*gg.y + bb.y;
        float y2 = (xv.z-mean)*rstd*gg.z + bb.z;
        float y3 = (xv.w-mean)*rstd*gg.w + bb.w;
        v0 += (y0-v0)*decay; v1 += (y1-v1)*decay; v2 += (y2-v2)*decay; v3 += (y3-v3)*decay;
        bool s0 = v0>=1.f, s1 = v1>=1.f, s2 = v2>=1.f, s3 = v3>=1.f;
        uint32_t lo = bf01(s0) | (bf01(s1)<<16), hi = bf01(s2) | (bf01(s3)<<16);
        ((uint2*)(h + r*512))[tid] = make_uint2(lo, hi);
        if (s0) v0=0.f; if (s1) v1=0.f; if (s2) v2=0.f; if (s3) v3=0.f;
    }
}

// ---------------- GEMM: C = A[M,K] @ W[N,K]^T, fused epilogues ----------------
// EP: 0 = QKV (LIF -> bit masks), 1 = proj (xt += acc+bias),
//     2 = fc1 (LIF+bias -> h4 bf16), 3 = fc2 (out = xt+acc+bias, transposed)
#define BM 128
#define BN 128
#define BK 32
#define STG 3
#define APAD 40
#define STAGE_BYTES (2*(BM*APAD*2))
#define GEMM_DSMEM (STG*STAGE_BYTES)

template<int EP>
__global__ void __launch_bounds__(256, 2) k_gemm(
        const __nv_bfloat16* __restrict__ A, const __nv_bfloat16* __restrict__ W,
        int N, int K,
        const float* __restrict__ lw, const float* __restrict__ bias,
        float* __restrict__ xt, float* __restrict__ out,
        uint32_t* __restrict__ qm, uint32_t* __restrict__ km, uint32_t* __restrict__ vm,
        __nv_bfloat16* __restrict__ h4){
    extern __shared__ char dsm[];
    const int tid  = threadIdx.x;
    const int lane = tid & 31, warp = tid >> 5;
    const int wm = warp >> 1, wn = warp & 1;
    const int bm = blockIdx.y*BM, bn = blockIdx.x*BN;
    const uint32_t sbase = smem_u32(dsm);
    const int nk = K >> 5;

    float acc[2][8][4];
#pragma unroll
    for (int i = 0; i < 2; i++)
#pragma unroll
        for (int j = 0; j < 8; j++)
#pragma unroll
            for (int r = 0; r < 4; r++) acc[i][j][r] = 0.f;

    auto load_stage = [&](int j){
        int s = j % STG;
        uint32_t sa = sbase + s*STAGE_BYTES;
        uint32_t sb = sa + (BM*APAD*2);
        int k0 = j*BK;
#pragma unroll
        for (int i = 0; i < 2; i++){
            int ch  = i*256 + tid;
            int row = ch >> 2, col = (ch & 3)*8;
            const char* ga = (const char*)(A + (size_t)(bm+row)*K + k0 + col);
            const char* gb = (const char*)(W + (size_t)(bn+row)*K + k0 + col);
            uint32_t da = sa + (uint32_t)(row*(APAD*2) + col*2);
            uint32_t db = sb + (uint32_t)(row*(APAD*2) + col*2);
            asm volatile("cp.async.cg.shared.global [%0], [%1], 16;" :: "r"(da), "l"(ga));
            asm volatile("cp.async.cg.shared.global [%0], [%1], 16;" :: "r"(db), "l"(gb));
        }
        asm volatile("cp.async.commit_group;");
    };

    load_stage(0);
    if (nk > 1) load_stage(1); else asm volatile("cp.async.commit_group;");

    for (int j = 0; j < nk; j++){
        asm volatile("cp.async.wait_group 1;");
        __syncthreads();
        int s = j % STG;
        uint32_t abase = sbase + s*STAGE_BYTES;
        uint32_t bbase = abase + (BM*APAD*2);
#pragma unroll
        for (int ks = 0; ks < BK; ks += 16){
            uint32_t a[2][4], b[4][4];
#pragma unroll
            for (int mt = 0; mt < 2; mt++){
                int row = wm*32 + mt*16 + (lane & 15);
                int col = ks + ((lane >> 4) << 3);
                uint32_t ad = abase + (uint32_t)(row*(APAD*2) + col*2);
                asm volatile("ldmatrix.sync.aligned.m8n8.x4.shared.b16 {%0,%1,%2,%3}, [%4];"
                             : "=r"(a[mt][0]), "=r"(a[mt][1]), "=r"(a[mt][2]), "=r"(a[mt][3])
                             : "r"(ad));
            }
#pragma unroll
            for (int ng = 0; ng < 4; ng++){
                int n = wn*64 + ng*16 + (lane & 7) + (((lane >> 4) & 1) << 3);
                int k = ks + (((lane >> 3) & 1) << 3);
                uint32_t bd = bbase + (uint32_t)(n*(APAD*2) + k*2);
                asm volatile("ldmatrix.sync.aligned.m8n8.x4.shared.b16 {%0,%1,%2,%3}, [%4];"
                             : "=r"(b[ng][0]), "=r"(b[ng][1]), "=r"(b[ng][2]), "=r"(b[ng][3])
                             : "r"(bd));
            }
#pragma unroll
            for (int mt = 0; mt < 2; mt++)
#pragma unroll
                for (int nf = 0; nf < 8; nf++){
                    uint32_t b0 = b[nf >> 1][(nf & 1)*2];
                    uint32_t b1 = b[nf >> 1][(nf & 1)*2 + 1];
                    asm volatile(
                        "mma.sync.aligned.m16n8k16.row.col.f32.bf16.bf16.f32 "
                        "{%0,%1,%2,%3}, {%4,%5,%6,%7}, {%8,%9}, {%0,%1,%2,%3};"
                        : "+f"(acc[mt][nf][0]), "+f"(acc[mt][nf][1]),
                          "+f"(acc[mt][nf][2]), "+f"(acc[mt][nf][3])
                        : "r"(a[mt][0]), "r"(a[mt][1]), "r"(a[mt][2]), "r"(a[mt][3]),
                          "r"(b0), "r"(b1));
                }
        }
        if (j + 2 < nk) load_stage(j + 2);
        else            asm volatile("cp.async.commit_group;");
        __syncthreads();
    }

    // ================= epilogues =================
    if (EP == 1){
        // proj: xt[r][col] += acc + bias[col]   (fragment-wise RMW, 32B sectors)
#pragma unroll
        for (int mt = 0; mt < 2; mt++){
            int r0 = bm + wm*32 + mt*16 + (lane >> 2);
#pragma unroll
            for (int nf = 0; nf < 8; nf++){
                int col = bn + wn*64 + nf*8 + (lane & 3)*2;
                float2 bb = *(const float2*)&bias[col];
                float2* p0 = (float2*)&xt[(size_t)r0*512 + col];
                float2 q0 = *p0;
                q0.x += acc[mt][nf][0] + bb.x; q0.y += acc[mt][nf][1] + bb.y;
                *p0 = q0;
                float2* p1 = (float2*)&xt[(size_t)(r0+8)*512 + col];
                float2 q1 = *p1;
                q1.x += acc[mt][nf][2] + bb.x; q1.y += acc[mt][nf][3] + bb.y;
                *p1 = q1;
            }
        }
        return;
    }

    if (EP == 3){
        // pre-add residual + bias fragment-wise
#pragma unroll
        for (int mt = 0; mt < 2; mt++){
            int r0 = bm + wm*32 + mt*16 + (lane >> 2);
#pragma unroll
            for (int nf = 0; nf < 8; nf++){
                int col = bn + wn*64 + nf*8 + (lane & 3)*2;
                float2 bb = *(const float2*)&bias[col];
                float2 x0 = *(const float2*)&xt[(size_t)r0*512 + col];
                float2 x1 = *(const float2*)&xt[(size_t)(r0+8)*512 + col];
                acc[mt][nf][0] += x0.x + bb.x; acc[mt][nf][1] += x0.y + bb.y;
                acc[mt][nf][2] += x1.x + bb.x; acc[mt][nf][3] += x1.y + bb.y;
            }
        }
    }

    // chunked smem epilogue (EP 0, 2, 3): 4 chunks of 32 cols
    float* es = (float*)dsm;
    for (int cc = 0; cc < 4; cc++){
        __syncthreads();
        if (wn == (cc >> 1)){
            int nfb = (cc & 1)*4;
#pragma unroll
            for (int mt = 0; mt < 2; mt++)
#pragma unroll
                for (int f = 0; f < 4; f++){
                    int nf = nfb + f;
                    int lc = f*8 + (lane & 3)*2;
                    int r0 = wm*32 + mt*16 + (lane >> 2);
                    es[r0*33 + lc]     = acc[mt][nf][0];
                    es[r0*33 + lc + 1] = acc[mt][nf][1];
                    es[(r0+8)*33 + lc]     = acc[mt][nf][2];
                    es[(r0+8)*33 + lc + 1] = acc[mt][nf][3];
                }
        }
        __syncthreads();
        int col0 = bn + cc*32;
        if (EP == 0){
            int isel = col0 >> 9, hh = (col0 >> 6) & 7, gsel = (col0 >> 5) & 1;
            float decay = sigmoidf_(lw[2 + isel]);
            uint32_t* mdst = (isel == 0) ? qm : (isel == 1) ? km : vm;
#pragma unroll
            for (int k2 = 0; k2 < 4; k2++){
                int j = k2*8 + warp;
                int tok = (bm >> 2) + j;
                int b = tok >> 8, n = tok & 255;
                float v = 0.f;
#pragma unroll
                for (int t = 0; t < 4; t++){
                    float val = es[(4*j + t)*33 + lane];
                    v += (val - v)*decay;
                    bool s = v >= 1.f;
                    uint32_t m = __ballot_sync(0xffffffffu, s);
                    if (s) v = 0.f;
                    if (lane == 0)
                        mdst[(((size_t)((t*16 + b)*8 + hh)*256 + n))*2 + gsel] = m;
                }
            }
        } else if (EP == 2){
            float decay = sigmoidf_(lw[7]);
#pragma unroll
            for (int k2 = 0; k2 < 4; k2++){
                int idx = k2*256 + tid;
                int j = idx >> 5, c = idx & 31;
                int col = col0 + c;
                float bvv = bias[col];
                int rb = bm + 4*j;
                float v = 0.f;
#pragma unroll
                for (int t = 0; t < 4; t++){
                    float val = es[(4*j + t)*33 + c] + bvv;
                    v += (val - v)*decay;
                    bool s = v >= 1.f;
                    h4[(size_t)(rb + t)*N + col] = __ushort_as_bfloat16(s ? (unsigned short)0x3F80 : (unsigned short)0);
                    if (s) v = 0.f;
                }
            }
        } else { // EP == 3: transposed store to out[t][b][col][n]
            int u = tid >> 1, half = tid & 1;
            int t = u >> 5, c = u & 31;
            int col = col0 + c;
            int tokb = bm >> 2;
            int b = tokb >> 8, n00 = (tokb & 255) + half*16;
            float* op = out + (((size_t)(t*16 + b)*512 + col)*256 + n00);
#pragma unroll
            for (int q4 = 0; q4 < 4; q4++){
                float4 vv;
                vv.x = es[(4*(half*16 + q4*4 + 0) + t)*33 + c];
                vv.y = es[(4*(half*16 + q4*4 + 1) + t)*33 + c];
                vv.z = es[(4*(half*16 + q4*4 + 2) + t)*33 + c];
                vv.w = es[(4*(half*16 + q4*4 + 3) + t)*33 + c];
                *(float4*)(op + q4*4) = vv;
            }
        }
    }
}

// ---------------- kv = k^T v from bit masks (ballot transpose + popc) ----------------
__global__ void __launch_bounds__(256) k_kv(const uint32_t* __restrict__ km,
                                            const uint32_t* __restrict__ vm,
                                            float* __restrict__ kvout){
    __shared__ uint32_t mk[256][2], mv[256][2];
    __shared__ uint32_t kb[64][8], vb[64][8];
    int tbh = blockIdx.x;
    int tid = threadIdx.x, lane = tid & 31, w = tid >> 5;
    uint2 a = ((const uint2*)km)[(size_t)tbh*256 + tid];
    uint2 c = ((const uint2*)vm)[(size_t)tbh*256 + tid];
    mk[tid][0] = a.x; mk[tid][1] = a.y;
    mv[tid][0] = c.x; mv[tid][1] = c.y;
    __syncthreads();
    uint32_t k0 = mk[w*32+lane][0], k1 = mk[w*32+lane][1];
    uint32_t v0 = mv[w*32+lane][0], v1 = mv[w*32+lane][1];
#pragma unroll
    for (int db = 0; db < 32; db++){
        uint32_t m;
        m = __ballot_sync(0xffffffffu, (k0 >> db) & 1); if (lane == 0) kb[db][w] = m;
        m = __ballot_sync(0xffffffffu, (k1 >> db) & 1); if (lane == 0) kb[32+db][w] = m;
        m = __ballot_sync(0xffffffffu, (v0 >> db) & 1); if (lane == 0) vb[db][w] = m;
        m = __ballot_sync(0xffffffffu, (v1 >> db) & 1); if (lane == 0) vb[32+db][w] = m;
    }
    __syncthreads();
    for (int o = tid; o < DH*DH; o += 256){
        int d = o >> 6, e = o & 63;
        int cnt = 0;
#pragma unroll
        for (int g = 0; g < 8; g++) cnt += __popc(kb[d][g] & vb[e][g]);
        kvout[(size_t)tbh*DH*DH + o] = (float)cnt;
    }
}

// ---------------- attention a = q@kv*scale + LIF -> bf16 spikes into h ----------------
__global__ void __launch_bounds__(256) k_attn_lif(const uint32_t* __restrict__ qm,
                                                  const float* __restrict__ kvin,
                                                  const float* __restrict__ lw,
                                                  __nv_bfloat16* __restrict__ h){
    __shared__ float skv[64][17];
    int bx = blockIdx.x;               // b*8 + h
    int b = bx >> 3, hh = bx & 7;
    int n = threadIdx.x;
    uint32_t mq[4][2];
#pragma unroll
    for (int t = 0; t < 4; t++){
        uint2 a = ((const uint2*)qm)[(size_t)((t*16+b)*8+hh)*256 + n];
        mq[t][0] = a.x; mq[t][1] = a.y;
    }
    float decay = sigmoidf_(lw[5]);
    size_t hbase = ((size_t)(b*256 + n)*4)*512 + hh*64;
    for (int eg = 0; eg < 4; eg++){
        float v[16];
#pragma unroll
        for (int e = 0; e < 16; e++) v[e] = 0.f;
        for (int t = 0; t < 4; t++){
            int tbh = (t*16 + b)*8 + hh;
            __syncthreads();
            { int d = n >> 2, io = (n & 3)*4;
              float4 f = *(const float4*)&kvin[(size_t)tbh*4096 + d*64 + eg*16 + io];
              skv[d][io] = f.x; skv[d][io+1] = f.y; skv[d][io+2] = f.z; skv[d][io+3] = f.w; }
            __syncthreads();
            float acc[16];
#pragma unroll
            for (int e = 0; e < 16; e++) acc[e] = 0.f;
#pragma unroll
            for (int g = 0; g < 2; g++){
                uint32_t m = mq[t][g];
                for (int db = 0; db < 32; db++){
                    if ((m >> db) & 1){
                        int d = g*32 + db;
#pragma unroll
                        for (int e = 0; e < 16; e++) acc[e] += skv[d][e];
                    }
                }
            }
            uint32_t pk[8];
#pragma unroll
            for (int e = 0; e < 16; e += 2){
                float a0 = acc[e]*0.125f, a1 = acc[e+1]*0.125f;
                v[e]   += (a0 - v[e])*decay;
                v[e+1] += (a1 - v[e+1])*decay;
                bool s0 = v[e] >= 1.f, s1 = v[e+1] >= 1.f;
                pk[e>>1] = bf01(s0) | (bf01(s1) << 16);
                if (s0) v[e] = 0.f;
                if (s1) v[e+1] = 0.f;
            }
            uint4* dst = (uint4*)(h + hbase + (size_t)t*512 + eg*16);
            dst[0] = make_uint4(pk[0], pk[1], pk[2], pk[3]);
            dst[1] = make_uint4(pk[4], pk[5], pk[6], pk[7]);
        }
    }
}

// ---------------- launch ----------------
extern "C" void kernel_launch(void* const* d_in, const int* in_sizes, int n_in,
                              void* d_out, int out_size){
    const float* x      = (const float*)d_in[0];
    const float* conv_w = (const float*)d_in[1];
    const float* conv_b = (const float*)d_in[2];
    const float* ln1_g  = (const float*)d_in[3];
    const float* ln1_b  = (const float*)d_in[4];
    const float* qkv_w  = (const float*)d_in[5];
    const float* proj_w = (const float*)d_in[6];
    const float* proj_b = (const float*)d_in[7];
    const float* ln2_g  = (const float*)d_in[8];
    const float* ln2_b  = (const float*)d_in[9];
    const float* fc1_w  = (const float*)d_in[10];
    const float* fc1_b  = (const float*)d_in[11];
    const float* fc2_w  = (const float*)d_in[12];
    const float* fc2_b  = (const float*)d_in[13];
    const float* lif_w  = (const float*)d_in[14];
    float* out = (float*)d_out;

    void *p_xt, *p_y, *p_kv, *p_s1, *p_h, *p_h4, *p_qm, *p_km, *p_vm,
         *p_wq, *p_wp, *p_w1, *p_w2;
    cudaGetSymbolAddress(&p_xt, g_xt);
    cudaGetSymbolAddress(&p_y,  g_y);
    cudaGetSymbolAddress(&p_kv, g_kv);
    cudaGetSymbolAddress(&p_s1, g_s1);
    cudaGetSymbolAddress(&p_h,  g_h);
    cudaGetSymbolAddress(&p_h4, g_h4);
    cudaGetSymbolAddress(&p_qm, g_qm);
    cudaGetSymbolAddress(&p_km, g_km);
    cudaGetSymbolAddress(&p_vm, g_vm);
    cudaGetSymbolAddress(&p_wq, g_wq);
    cudaGetSymbolAddress(&p_wp, g_wp);
    cudaGetSymbolAddress(&p_w1, g_w1);
    cudaGetSymbolAddress(&p_w2, g_w2);

    float* xt = (float*)p_xt;
    float* y  = (float*)p_y;
    float* kv = (float*)p_kv;
    unsigned char* s1 = (unsigned char*)p_s1;
    __nv_bfloat16* h  = (__nv_bfloat16*)p_h;
    __nv_bfloat16* h4 = (__nv_bfloat16*)p_h4;
    uint32_t* qm = (uint32_t*)p_qm;
    uint32_t* km = (uint32_t*)p_km;
    uint32_t* vm = (uint32_t*)p_vm;
    __nv_bfloat16* wq = (__nv_bfloat16*)p_wq;
    __nv_bfloat16* wp = (__nv_bfloat16*)p_wp;
    __nv_bfloat16* w1 = (__nv_bfloat16*)p_w1;
    __nv_bfloat16* w2 = (__nv_bfloat16*)p_w2;

    cudaFuncSetAttribute(k_gemm<0>, cudaFuncAttributeMaxDynamicSharedMemorySize, GEMM_DSMEM);
    cudaFuncSetAttribute(k_gemm<1>, cudaFuncAttributeMaxDynamicSharedMemorySize, GEMM_DSMEM);
    cudaFuncSetAttribute(k_gemm<2>, cudaFuncAttributeMaxDynamicSharedMemorySize, GEMM_DSMEM);
    cudaFuncSetAttribute(k_gemm<3>, cudaFuncAttributeMaxDynamicSharedMemorySize, GEMM_DSMEM);

    // 1) weights -> bf16
    k_cvt_all<<<3072, 256>>>(qkv_w, proj_w, fc1_w, fc2_w, wq, wp, w1, w2);
    // 2) LIF on x -> s1
    k_lif1<<<(PLANE/4)/256, 256>>>(x, lif_w, (uint32_t*)s1);
    // 3) depthwise conv + residual -> y
    k_conv<<<(TT*PLANE/16)/256, 256>>>(x, s1, conv_w, conv_b, y);
    // 4) transpose -> xt rows (bn*4+t)
    k_tr<<<dim3(4, 8, 64), 256>>>(y, xt);
    // 5) LN1 + LIF -> h
    k_ln_lif<<<BNROWS, 128>>>(xt, ln1_g, ln1_b, lif_w, 1, h);
    // 6) QKV GEMM + LIF -> bit masks
    k_gemm<0><<<dim3(12, 128), 256, GEMM_DSMEM>>>(h, wq, 3*CC, CC, lif_w, nullptr,
                                                  nullptr, nullptr, qm, km, vm, nullptr);
    // 7) kv = k^T v
    k_kv<<<TT*BB*NHEAD, 256>>>(km, vm, kv);
    // 8) a = q@kv*scale + LIF -> h
    k_attn_lif<<<BB*NHEAD, 256>>>(qm, kv, lif_w, h);
    // 9) proj GEMM: xt += h@Wp^T + proj_b
    k_gemm<1><<<dim3(4, 128), 256, GEMM_DSMEM>>>(h, wp, CC, CC, lif_w, proj_b,
                                                 xt, nullptr, nullptr, nullptr, nullptr, nullptr);
    // 10) LN2 + LIF -> h
    k_ln_lif<<<BNROWS, 128>>>(xt, ln2_g, ln2_b, lif_w, 6, h);
    // 11) FC1 GEMM + bias + LIF -> h4
    k_gemm<2><<<dim3(16, 128), 256, GEMM_DSMEM>>>(h, w1, HID, CC, lif_w, fc1_b,
                                                  nullptr, nullptr, nullptr, nullptr, nullptr, h4);
    // 12) FC2 GEMM + bias + residual, transposed -> out
    k_gemm<3><<<dim3(4, 128), 256, GEMM_DSMEM>>>(h4, w2, CC, HID, lif_w, fc2_b,
                                                 xt, out, nullptr, nullptr, nullptr, nullptr);
}

// round 5
// speedup vs baseline: 1.9786x; 1.0544x over previous
#include <cuda_runtime.h>
#include <cuda_bf16.h>
#include <cuda_fp8.h>
#include <cstdint>

// ---------------- Problem constants ----------------
#define TT 4
#define BB 16
#define CC 512
#define NN 256
#define NHEAD 8
#define DH 64
#define HID 2048
#define MROWS (TT*BB*NN)  // 16384
#define BNROWS (BB*NN)    // 4096
#define PLANE (BB*CC*NN)  // 2097152

// Row ordering for token-major tensors: r = bn*4 + t

// ---------------- Static device scratch ----------------
__device__ float          g_xt [(size_t)MROWS*CC];
__device__ float          g_y  [(size_t)TT*PLANE];
__device__ float          g_kv [(size_t)TT*BB*NHEAD*DH*DH];
__device__ unsigned char  g_h  [(size_t)MROWS*CC];    // e4m3 spikes
__device__ unsigned char  g_h4 [(size_t)MROWS*HID];   // e4m3 spikes
__device__ uint32_t       g_qm [(size_t)TT*BB*NHEAD*NN*2];
__device__ uint32_t       g_km [(size_t)TT*BB*NHEAD*NN*2];
__device__ uint32_t       g_vm [(size_t)TT*BB*NHEAD*NN*2];
__device__ unsigned char  g_wq [(size_t)3*CC*CC];     // e4m3 weights
__device__ unsigned char  g_wp [(size_t)CC*CC];
__device__ unsigned char  g_w1 [(size_t)HID*CC];
__device__ unsigned char  g_w2 [(size_t)CC*HID];

__device__ __forceinline__ float sigmoidf_(float w){ return 1.f/(1.f+expf(-w)); }
__device__ __forceinline__ uint32_t smem_u32(const void* p){
    uint32_t a;
    asm("{ .reg .u64 t; cvta.to.shared.u64 t, %1; cvt.u32.u64 %0, t; }" : "=r"(a) : "l"(p));
    return a;
}
__device__ __forceinline__ uint32_t f2e4(float f){
    return (uint32_t)__nv_cvt_float_to_fp8(f, __NV_SATFINITE, __NV_E4M3);
}
#define FP8_ONE 0x38u

// ---------------- all weights -> e4m3, one kernel ----------------
__global__ void k_cvt_all(const float* __restrict__ a0, const float* __restrict__ a1,
                          const float* __restrict__ a2, const float* __restrict__ a3,
                          uint8_t* __restrict__ d0, uint8_t* __restrict__ d1,
                          uint8_t* __restrict__ d2, uint8_t* __restrict__ d3){
    int i = blockIdx.x*blockDim.x + threadIdx.x;   // float4 index
    const int n0 = 196608, n1 = 65536, n2 = 262144, n3 = 262144;
    const float* s; uint8_t* d; int off;
    if      (i < n0){            s=a0; d=d0; off=i; }
    else if (i < n0+n1){         s=a1; d=d1; off=i-n0; }
    else if (i < n0+n1+n2){      s=a2; d=d2; off=i-n0-n1; }
    else if (i < n0+n1+n2+n3){   s=a3; d=d3; off=i-n0-n1-n2; }
    else return;
    float4 v = ((const float4*)s)[off];
    uint32_t w = f2e4(v.x) | (f2e4(v.y)<<8) | (f2e4(v.z)<<16) | (f2e4(v.w)<<24);
    ((uint32_t*)d)[off] = w;
}

// ---------------- fused LIF(x) + depthwise 3x3 conv + residual ----------------
// one block = one (b, c) 16x16 plane across all T
__global__ void __launch_bounds__(256) k_lifconv(
        const float* __restrict__ x, const float* __restrict__ lw,
        const float* __restrict__ cw, const float* __restrict__ cb,
        float* __restrict__ y){
    __shared__ unsigned char sp[4][256];
    int b = blockIdx.x >> 9, c = blockIdx.x & 511;
    int px = threadIdx.x;
    size_t base = ((size_t)b*512 + c)*256 + px;
    float decay = sigmoidf_(lw[0]);
    float xv[4];
#pragma unroll
    for (int t = 0; t < 4; t++) xv[t] = x[(size_t)t*PLANE + base];
    float v = 0.f;
#pragma unroll
    for (int t = 0; t < 4; t++){
        v += (xv[t] - v)*decay;
        unsigned char s = (v >= 1.f);
        sp[t][px] = s;
        if (s) v = 0.f;
    }
    __syncthreads();
    float wk[9];
#pragma unroll
    for (int j = 0; j < 9; j++) wk[j] = cw[c*9 + j];
    float bias = cb[c];
    int h = px >> 4, w = px & 15;
#pragma unroll
    for (int t = 0; t < 4; t++){
        float acc = bias;
#pragma unroll
        for (int dy = -1; dy <= 1; dy++){
            int hh = h + dy; if ((unsigned)hh >= 16u) continue;
#pragma unroll
            for (int dx = -1; dx <= 1; dx++){
                int ww = w + dx; if ((unsigned)ww >= 16u) continue;
                acc += wk[(dy+1)*3 + (dx+1)] * (float)sp[t][hh*16 + ww];
            }
        }
        y[(size_t)t*PLANE + base] = xv[t] + acc;
    }
}

// ---------------- transpose [tb][C][N] -> xt rows (bn*4+t) ----------------
__global__ void __launch_bounds__(256) k_tr(const float* __restrict__ y, float* __restrict__ xt){
    __shared__ float s[64][65];
    int bz = blockIdx.z;                 // t*16+b
    int t = bz >> 4, b = bz & 15;
    int n0 = blockIdx.x*64, c0 = blockIdx.y*64;
    int tid = threadIdx.x;
    const float* src = y + (size_t)bz*512*256;
#pragma unroll
    for (int it = 0; it < 4; it++){
        int cr = it*16 + (tid >> 4), ng = (tid & 15)*4;
        float4 f = *(const float4*)&src[(size_t)(c0+cr)*256 + n0 + ng];
        s[cr][ng+0] = f.x; s[cr][ng+1] = f.y; s[cr][ng+2] = f.z; s[cr][ng+3] = f.w;
    }
    __syncthreads();
#pragma unroll
    for (int it = 0; it < 4; it++){
        int nr = it*16 + (tid >> 4), cg = (tid & 15)*4;
        size_t row = (size_t)(b*256 + n0 + nr)*4 + t;
        float4 f = make_float4(s[cg][nr], s[cg+1][nr], s[cg+2][nr], s[cg+3][nr]);
        *(float4*)&xt[row*512 + c0 + cg] = f;
    }
}

// ---------------- LayerNorm(C) + LIF over T -> e4m3 spikes ----------------
__global__ void __launch_bounds__(128) k_ln_lif(
        const float* __restrict__ xt, const float* __restrict__ g, const float* __restrict__ bv,
        const float* __restrict__ lw, int lwi, uint8_t* __restrict__ h){
    int bn = blockIdx.x, tid = threadIdx.x;
    int lane = tid & 31, w = tid >> 5;
    __shared__ float sw_[4][4], sq_[4][4];
    float decay = sigmoidf_(lw[lwi]);
    float4 gg = *(const float4*)&g[tid*4];
    float4 bb = *(const float4*)&bv[tid*4];
    float4 xv[4];
#pragma unroll
    for (int t = 0; t < 4; t++)
        xv[t] = *(const float4*)&xt[((size_t)bn*4 + t)*512 + tid*4];
    float v0=0,v1=0,v2=0,v3=0;
#pragma unroll
    for (int t = 0; t < 4; t++){
        float4 xw = xv[t];
        float s = xw.x+xw.y+xw.z+xw.w;
        float q = xw.x*xw.x+xw.y*xw.y+xw.z*xw.z+xw.w*xw.w;
#pragma unroll
        for (int o = 16; o > 0; o >>= 1){
            s += __shfl_xor_sync(0xffffffffu, s, o);
            q += __shfl_xor_sync(0xffffffffu, q, o);
        }
        if (lane == 0){ sw_[t][w] = s; sq_[t][w] = q; }
        __syncthreads();
        float ts = sw_[t][0]+sw_[t][1]+sw_[t][2]+sw_[t][3];
        float tq = sq_[t][0]+sq_[t][1]+sq_[t][2]+sq_[t][3];
        float mean = ts*(1.f/512.f);
        float var  = tq*(1.f/512.f) - mean*mean;
        float rstd = rsqrtf(var + 1e-5f);
        float y0 = (xw.x-mean)*rstd*gg.x + bb.x;
        float y1 = (xw.y-mean)*rstd*gg.y + bb.y;
        float y2 = (xw.z-mean)*rstd*gg.z + bb.z;
        float y3 = (xw.w-mean)*rstd*gg.w + bb.w;
        v0 += (y0-v0)*decay; v1 += (y1-v1)*decay; v2 += (y2-v2)*decay; v3 += (y3-v3)*decay;
        bool s0 = v0>=1.f, s1 = v1>=1.f, s2 = v2>=1.f, s3 = v3>=1.f;
        uint32_t pw = (s0?FP8_ONE:0u) | ((s1?FP8_ONE:0u)<<8)
                    | ((s2?FP8_ONE:0u)<<16) | ((s3?FP8_ONE:0u)<<24);
        ((uint32_t*)(h + ((size_t)bn*4 + t)*512))[tid] = pw;
        if (s0) v0=0.f; if (s1) v1=0.f; if (s2) v2=0.f; if (s3) v3=0.f;
        __syncthreads();
    }
}

// ---------------- FP8 GEMM: C = A[M,K] @ W[N,K]^T (e4m3 x e4m3 -> fp32) ----------------
// EP: 0 = QKV (LIF -> bit masks), 1 = proj (xt += acc+bias),
//     2 = fc1 (LIF+bias -> h4 e4m3), 3 = fc2 (out = xt+acc+bias, transposed)
#define BMT 128
#define BNT 128
#define BKB 64                    // K bytes per stage
#define STG 3
#define ROWB 80                   // padded smem row bytes (64 data + 16 pad)
#define STAGE_BYTES (2*BMT*ROWB)  // 20480
#define GEMM_DSMEM (STG*STAGE_BYTES)

template<int EP>
__global__ void __launch_bounds__(256, 2) k_gemm(
        const uint8_t* __restrict__ A, const uint8_t* __restrict__ W,
        int N, int K,
        const float* __restrict__ lw, const float* __restrict__ bias,
        float* __restrict__ xt, float* __restrict__ out,
        uint32_t* __restrict__ qm, uint32_t* __restrict__ km, uint32_t* __restrict__ vm,
        uint8_t* __restrict__ h4){
    extern __shared__ char dsm[];
    const int tid  = threadIdx.x;
    const int lane = tid & 31, warp = tid >> 5;
    const int wm = warp >> 1, wn = warp & 1;
    const int bm = blockIdx.y*BMT, bn = blockIdx.x*BNT;
    const uint32_t sbase = smem_u32(dsm);
    const int nk = K >> 6;

    float acc[2][8][4];
#pragma unroll
    for (int i = 0; i < 2; i++)
#pragma unroll
        for (int j = 0; j < 8; j++)
#pragma unroll
            for (int r = 0; r < 4; r++) acc[i][j][r] = 0.f;

    auto load_stage = [&](int j){
        int s = j % STG;
        uint32_t sa = sbase + s*STAGE_BYTES;
        uint32_t sb = sa + BMT*ROWB;
        int k0 = j*BKB;
#pragma unroll
        for (int i = 0; i < 2; i++){
            int ch  = i*256 + tid;             // 0..511
            int row = ch >> 2, colb = (ch & 3)*16;
            const char* ga = (const char*)(A + (size_t)(bm+row)*K + k0 + colb);
            const char* gb = (const char*)(W + (size_t)(bn+row)*K + k0 + colb);
            uint32_t da = sa + (uint32_t)(row*ROWB + colb);
            uint32_t db = sb + (uint32_t)(row*ROWB + colb);
            asm volatile("cp.async.cg.shared.global [%0], [%1], 16;" :: "r"(da), "l"(ga));
            asm volatile("cp.async.cg.shared.global [%0], [%1], 16;" :: "r"(db), "l"(gb));
        }
        asm volatile("cp.async.commit_group;");
    };

    load_stage(0);
    if (nk > 1) load_stage(1); else asm volatile("cp.async.commit_group;");

    for (int j = 0; j < nk; j++){
        asm volatile("cp.async.wait_group 1;");
        __syncthreads();
        int s = j % STG;
        uint32_t abase = sbase + s*STAGE_BYTES;
        uint32_t bbase = abase + BMT*ROWB;
#pragma unroll
        for (int ks = 0; ks < 2; ks++){            // two k32 steps (32 bytes each)
            uint32_t a[2][4], b[4][4];
#pragma unroll
            for (int mt = 0; mt < 2; mt++){
                int row = wm*32 + mt*16 + (lane & 15);
                int colb = ks*32 + ((lane >> 4) << 4);
                uint32_t ad = abase + (uint32_t)(row*ROWB + colb);
                asm volatile("ldmatrix.sync.aligned.m8n8.x4.shared.b16 {%0,%1,%2,%3}, [%4];"
                             : "=r"(a[mt][0]), "=r"(a[mt][1]), "=r"(a[mt][2]), "=r"(a[mt][3])
                             : "r"(ad));
            }
#pragma unroll
            for (int ng = 0; ng < 4; ng++){
                int n = wn*64 + ng*16 + (lane & 7) + (((lane >> 4) & 1) << 3);
                int colb = ks*32 + (((lane >> 3) & 1) << 4);
                uint32_t bd = bbase + (uint32_t)(n*ROWB + colb);
                asm volatile("ldmatrix.sync.aligned.m8n8.x4.shared.b16 {%0,%1,%2,%3}, [%4];"
                             : "=r"(b[ng][0]), "=r"(b[ng][1]), "=r"(b[ng][2]), "=r"(b[ng][3])
                             : "r"(bd));
            }
#pragma unroll
            for (int mt = 0; mt < 2; mt++)
#pragma unroll
                for (int nf = 0; nf < 8; nf++){
                    uint32_t b0 = b[nf >> 1][(nf & 1)*2];
                    uint32_t b1 = b[nf >> 1][(nf & 1)*2 + 1];
                    asm volatile(
                        "mma.sync.aligned.m16n8k32.row.col.f32.e4m3.e4m3.f32 "
                        "{%0,%1,%2,%3}, {%4,%5,%6,%7}, {%8,%9}, {%0,%1,%2,%3};"
                        : "+f"(acc[mt][nf][0]), "+f"(acc[mt][nf][1]),
                          "+f"(acc[mt][nf][2]), "+f"(acc[mt][nf][3])
                        : "r"(a[mt][0]), "r"(a[mt][1]), "r"(a[mt][2]), "r"(a[mt][3]),
                          "r"(b0), "r"(b1));
                }
        }
        if (j + 2 < nk) load_stage(j + 2);
        else            asm volatile("cp.async.commit_group;");
        __syncthreads();
    }

    // ================= epilogues =================
    if (EP == 1){
#pragma unroll
        for (int mt = 0; mt < 2; mt++){
            int r0 = bm + wm*32 + mt*16 + (lane >> 2);
#pragma unroll
            for (int nf = 0; nf < 8; nf++){
                int col = bn + wn*64 + nf*8 + (lane & 3)*2;
                float2 bb = *(const float2*)&bias[col];
                float2* p0 = (float2*)&xt[(size_t)r0*512 + col];
                float2 q0 = *p0;
                q0.x += acc[mt][nf][0] + bb.x; q0.y += acc[mt][nf][1] + bb.y;
                *p0 = q0;
                float2* p1 = (float2*)&xt[(size_t)(r0+8)*512 + col];
                float2 q1 = *p1;
                q1.x += acc[mt][nf][2] + bb.x; q1.y += acc[mt][nf][3] + bb.y;
                *p1 = q1;
            }
        }
        return;
    }

    if (EP == 3){
#pragma unroll
        for (int mt = 0; mt < 2; mt++){
            int r0 = bm + wm*32 + mt*16 + (lane >> 2);
#pragma unroll
            for (int nf = 0; nf < 8; nf++){
                int col = bn + wn*64 + nf*8 + (lane & 3)*2;
                float2 bb = *(const float2*)&bias[col];
                float2 x0 = *(const float2*)&xt[(size_t)r0*512 + col];
                float2 x1 = *(const float2*)&xt[(size_t)(r0+8)*512 + col];
                acc[mt][nf][0] += x0.x + bb.x; acc[mt][nf][1] += x0.y + bb.y;
                acc[mt][nf][2] += x1.x + bb.x; acc[mt][nf][3] += x1.y + bb.y;
            }
        }
    }

    // chunked smem epilogue (EP 0, 2, 3): 4 chunks of 32 cols
    float* es = (float*)dsm;
    for (int cc = 0; cc < 4; cc++){
        __syncthreads();
        if (wn == (cc >> 1)){
            int nfb = (cc & 1)*4;
#pragma unroll
            for (int mt = 0; mt < 2; mt++)
#pragma unroll
                for (int f = 0; f < 4; f++){
                    int nf = nfb + f;
                    int lc = f*8 + (lane & 3)*2;
                    int r0 = wm*32 + mt*16 + (lane >> 2);
                    es[r0*33 + lc]     = acc[mt][nf][0];
                    es[r0*33 + lc + 1] = acc[mt][nf][1];
                    es[(r0+8)*33 + lc]     = acc[mt][nf][2];
                    es[(r0+8)*33 + lc + 1] = acc[mt][nf][3];
                }
        }
        __syncthreads();
        int col0 = bn + cc*32;
        if (EP == 0){
            int isel = col0 >> 9, hh = (col0 >> 6) & 7, gsel = (col0 >> 5) & 1;
            float decay = sigmoidf_(lw[2 + isel]);
            uint32_t* mdst = (isel == 0) ? qm : (isel == 1) ? km : vm;
#pragma unroll
            for (int k2 = 0; k2 < 4; k2++){
                int j = k2*8 + warp;
                int tok = (bm >> 2) + j;
                int b = tok >> 8, n = tok & 255;
                float v = 0.f;
#pragma unroll
                for (int t = 0; t < 4; t++){
                    float val = es[(4*j + t)*33 + lane];
                    v += (val - v)*decay;
                    bool s = v >= 1.f;
                    uint32_t m = __ballot_sync(0xffffffffu, s);
                    if (s) v = 0.f;
                    if (lane == 0)
                        mdst[(((size_t)((t*16 + b)*8 + hh)*256 + n))*2 + gsel] = m;
                }
            }
        } else if (EP == 2){
            float decay = sigmoidf_(lw[7]);
#pragma unroll
            for (int k2 = 0; k2 < 4; k2++){
                int idx = k2*256 + tid;
                int j = idx >> 5, c = idx & 31;
                int col = col0 + c;
                float bvv = bias[col];
                int rb = bm + 4*j;
                float v = 0.f;
#pragma unroll
                for (int t = 0; t < 4; t++){
                    float val = es[(4*j + t)*33 + c] + bvv;
                    v += (val - v)*decay;
                    bool s = v >= 1.f;
                    h4[(size_t)(rb + t)*N + col] = s ? (uint8_t)FP8_ONE : (uint8_t)0;
                    if (s) v = 0.f;
                }
            }
        } else { // EP == 3
            int u = tid >> 1, half = tid & 1;
            int t = u >> 5, c = u & 31;
            int col = col0 + c;
            int tokb = bm >> 2;
            int b = tokb >> 8, n00 = (tokb & 255) + half*16;
            float* op = out + (((size_t)(t*16 + b)*512 + col)*256 + n00);
#pragma unroll
            for (int q4 = 0; q4 < 4; q4++){
                float4 vv;
                vv.x = es[(4*(half*16 + q4*4 + 0) + t)*33 + c];
                vv.y = es[(4*(half*16 + q4*4 + 1) + t)*33 + c];
                vv.z = es[(4*(half*16 + q4*4 + 2) + t)*33 + c];
                vv.w = es[(4*(half*16 + q4*4 + 3) + t)*33 + c];
                *(float4*)(op + q4*4) = vv;
            }
        }
    }
}

// ---------------- kv = k^T v from bit masks ----------------
__global__ void __launch_bounds__(256) k_kv(const uint32_t* __restrict__ km,
                                            const uint32_t* __restrict__ vm,
                                            float* __restrict__ kvout){
    __shared__ uint32_t mk[256][2], mv[256][2];
    __shared__ uint32_t kb[64][8], vb[64][8];
    int tbh = blockIdx.x;
    int tid = threadIdx.x, lane = tid & 31, w = tid >> 5;
    uint2 a = ((const uint2*)km)[(size_t)tbh*256 + tid];
    uint2 c = ((const uint2*)vm)[(size_t)tbh*256 + tid];
    mk[tid][0] = a.x; mk[tid][1] = a.y;
    mv[tid][0] = c.x; mv[tid][1] = c.y;
    __syncthreads();
    uint32_t k0 = mk[w*32+lane][0], k1 = mk[w*32+lane][1];
    uint32_t v0 = mv[w*32+lane][0], v1 = mv[w*32+lane][1];
#pragma unroll
    for (int db = 0; db < 32; db++){
        uint32_t m;
        m = __ballot_sync(0xffffffffu, (k0 >> db) & 1); if (lane == 0) kb[db][w] = m;
        m = __ballot_sync(0xffffffffu, (k1 >> db) & 1); if (lane == 0) kb[32+db][w] = m;
        m = __ballot_sync(0xffffffffu, (v0 >> db) & 1); if (lane == 0) vb[db][w] = m;
        m = __ballot_sync(0xffffffffu, (v1 >> db) & 1); if (lane == 0) vb[32+db][w] = m;
    }
    __syncthreads();
    for (int o = tid; o < DH*DH; o += 256){
        int d = o >> 6, e = o & 63;
        int cnt = 0;
#pragma unroll
        for (int g = 0; g < 8; g++) cnt += __popc(kb[d][g] & vb[e][g]);
        kvout[(size_t)tbh*DH*DH + o] = (float)cnt;
    }
}

// ---------------- attention a = q@kv*scale + LIF -> e4m3 spikes into h ----------------
__global__ void __launch_bounds__(256) k_attn_lif(const uint32_t* __restrict__ qm,
                                                  const float* __restrict__ kvin,
                                                  const float* __restrict__ lw,
                                                  uint8_t* __restrict__ h){
    __shared__ float skv[64][17];
    int bx = blockIdx.x;               // b*8 + h
    int b = bx >> 3, hh = bx & 7;
    int n = threadIdx.x;
    uint32_t mq[4][2];
#pragma unroll
    for (int t = 0; t < 4; t++){
        uint2 a = ((const uint2*)qm)[(size_t)((t*16+b)*8+hh)*256 + n];
        mq[t][0] = a.x; mq[t][1] = a.y;
    }
    float decay = sigmoidf_(lw[5]);
    size_t hbase = ((size_t)(b*256 + n)*4)*512 + hh*64;
    for (int eg = 0; eg < 4; eg++){
        float v[16];
#pragma unroll
        for (int e = 0; e < 16; e++) v[e] = 0.f;
        for (int t = 0; t < 4; t++){
            int tbh = (t*16 + b)*8 + hh;
            __syncthreads();
            { int d = n >> 2, io = (n & 3)*4;
              float4 f = *(const float4*)&kvin[(size_t)tbh*4096 + d*64 + eg*16 + io];
              skv[d][io] = f.x; skv[d][io+1] = f.y; skv[d][io+2] = f.z; skv[d][io+3] = f.w; }
            __syncthreads();
            float acc[16];
#pragma unroll
            for (int e = 0; e < 16; e++) acc[e] = 0.f;
#pragma unroll
            for (int g = 0; g < 2; g++){
                uint32_t m = mq[t][g];
                for (int db = 0; db < 32; db++){
                    if ((m >> db) & 1){
                        int d = g*32 + db;
#pragma unroll
                        for (int e = 0; e < 16; e++) acc[e] += skv[d][e];
                    }
                }
            }
            uint32_t pw[4];
#pragma unroll
            for (int qq = 0; qq < 4; qq++){
                uint32_t wv = 0;
#pragma unroll
                for (int e2 = 0; e2 < 4; e2++){
                    int e = qq*4 + e2;
                    float a0 = acc[e]*0.125f;
                    v[e] += (a0 - v[e])*decay;
                    bool s = v[e] >= 1.f;
                    wv |= (s ? FP8_ONE : 0u) << (e2*8);
                    if (s) v[e] = 0.f;
                }
                pw[qq] = wv;
            }
            *(uint4*)(h + hbase + (size_t)t*512 + eg*16) = make_uint4(pw[0],pw[1],pw[2],pw[3]);
        }
    }
}

// ---------------- launch ----------------
extern "C" void kernel_launch(void* const* d_in, const int* in_sizes, int n_in,
                              void* d_out, int out_size){
    const float* x      = (const float*)d_in[0];
    const float* conv_w = (const float*)d_in[1];
    const float* conv_b = (const float*)d_in[2];
    const float* ln1_g  = (const float*)d_in[3];
    const float* ln1_b  = (const float*)d_in[4];
    const float* qkv_w  = (const float*)d_in[5];
    const float* proj_w = (const float*)d_in[6];
    const float* proj_b = (const float*)d_in[7];
    const float* ln2_g  = (const float*)d_in[8];
    const float* ln2_b  = (const float*)d_in[9];
    const float* fc1_w  = (const float*)d_in[10];
    const float* fc1_b  = (const float*)d_in[11];
    const float* fc2_w  = (const float*)d_in[12];
    const float* fc2_b  = (const float*)d_in[13];
    const float* lif_w  = (const float*)d_in[14];
    float* out = (float*)d_out;

    void *p_xt, *p_y, *p_kv, *p_h, *p_h4, *p_qm, *p_km, *p_vm,
         *p_wq, *p_wp, *p_w1, *p_w2;
    cudaGetSymbolAddress(&p_xt, g_xt);
    cudaGetSymbolAddress(&p_y,  g_y);
    cudaGetSymbolAddress(&p_kv, g_kv);
    cudaGetSymbolAddress(&p_h,  g_h);
    cudaGetSymbolAddress(&p_h4, g_h4);
    cudaGetSymbolAddress(&p_qm, g_qm);
    cudaGetSymbolAddress(&p_km, g_km);
    cudaGetSymbolAddress(&p_vm, g_vm);
    cudaGetSymbolAddress(&p_wq, g_wq);
    cudaGetSymbolAddress(&p_wp, g_wp);
    cudaGetSymbolAddress(&p_w1, g_w1);
    cudaGetSymbolAddress(&p_w2, g_w2);

    float* xt = (float*)p_xt;
    float* y  = (float*)p_y;
    float* kv = (float*)p_kv;
    uint8_t* h  = (uint8_t*)p_h;
    uint8_t* h4 = (uint8_t*)p_h4;
    uint32_t* qm = (uint32_t*)p_qm;
    uint32_t* km = (uint32_t*)p_km;
    uint32_t* vm = (uint32_t*)p_vm;
    uint8_t* wq = (uint8_t*)p_wq;
    uint8_t* wp = (uint8_t*)p_wp;
    uint8_t* w1 = (uint8_t*)p_w1;
    uint8_t* w2 = (uint8_t*)p_w2;

    cudaFuncSetAttribute(k_gemm<0>, cudaFuncAttributeMaxDynamicSharedMemorySize, GEMM_DSMEM);
    cudaFuncSetAttribute(k_gemm<1>, cudaFuncAttributeMaxDynamicSharedMemorySize, GEMM_DSMEM);
    cudaFuncSetAttribute(k_gemm<2>, cudaFuncAttributeMaxDynamicSharedMemorySize, GEMM_DSMEM);
    cudaFuncSetAttribute(k_gemm<3>, cudaFuncAttributeMaxDynamicSharedMemorySize, GEMM_DSMEM);

    // 1) weights -> e4m3
    k_cvt_all<<<3072, 256>>>(qkv_w, proj_w, fc1_w, fc2_w, wq, wp, w1, w2);
    // 2) fused LIF(x) + conv + residual -> y
    k_lifconv<<<BB*CC, 256>>>(x, lif_w, conv_w, conv_b, y);
    // 3) transpose -> xt rows (bn*4+t)
    k_tr<<<dim3(4, 8, 64), 256>>>(y, xt);
    // 4) LN1 + LIF -> h
    k_ln_lif<<<BNROWS, 128>>>(xt, ln1_g, ln1_b, lif_w, 1, h);
    // 5) QKV GEMM + LIF -> bit masks
    k_gemm<0><<<dim3(12, 128), 256, GEMM_DSMEM>>>(h, wq, 3*CC, CC, lif_w, nullptr,
                                                  nullptr, nullptr, qm, km, vm, nullptr);
    // 6) kv = k^T v
    k_kv<<<TT*BB*NHEAD, 256>>>(km, vm, kv);
    // 7) a = q@kv*scale + LIF -> h
    k_attn_lif<<<BB*NHEAD, 256>>>(qm, kv, lif_w, h);
    // 8) proj GEMM: xt += h@Wp^T + proj_b
    k_gemm<1><<<dim3(4, 128), 256, GEMM_DSMEM>>>(h, wp, CC, CC, lif_w, proj_b,
                                                 xt, nullptr, nullptr, nullptr, nullptr, nullptr);
    // 9) LN2 + LIF -> h
    k_ln_lif<<<BNROWS, 128>>>(xt, ln2_g, ln2_b, lif_w, 6, h);
    // 10) FC1 GEMM + bias + LIF -> h4
    k_gemm<2><<<dim3(16, 128), 256, GEMM_DSMEM>>>(h, w1, HID, CC, lif_w, fc1_b,
                                                  nullptr, nullptr, nullptr, nullptr, nullptr, h4);
    // 11) FC2 GEMM + bias + residual, transposed -> out
    k_gemm<3><<<dim3(4, 128), 256, GEMM_DSMEM>>>(h4, w2, CC, HID, lif_w, fc2_b,
                                                 xt, out, nullptr, nullptr, nullptr, nullptr);
}

// round 6
// speedup vs baseline: 2.4979x; 1.2624x over previous
#include <cuda_runtime.h>
#include <cuda_bf16.h>
#include <cuda_fp8.h>
#include <cstdint>

// ---------------- Problem constants ----------------
#define TT 4
#define BB 16
#define CC 512
#define NN 256
#define NHEAD 8
#define DH 64
#define HID 2048
#define MROWS (TT*BB*NN)  // 16384
#define BNROWS (BB*NN)    // 4096
#define PLANE (BB*CC*NN)  // 2097152

// Row ordering for token-major tensors: r = bn*4 + t

// ---------------- Static device scratch ----------------
__device__ float          g_xt [(size_t)MROWS*CC];
__device__ float          g_y  [(size_t)TT*PLANE];
__device__ float          g_kv [(size_t)TT*BB*NHEAD*DH*DH];
__device__ unsigned char  g_h  [(size_t)MROWS*CC];    // e4m3 spikes
__device__ unsigned char  g_h4 [(size_t)MROWS*HID];   // e4m3 spikes
__device__ uint32_t       g_qm [(size_t)TT*BB*NHEAD*NN*2];
__device__ uint32_t       g_km [(size_t)TT*BB*NHEAD*NN*2];
__device__ uint32_t       g_vm [(size_t)TT*BB*NHEAD*NN*2];
__device__ unsigned char  g_wq [(size_t)3*CC*CC];     // e4m3 weights
__device__ unsigned char  g_wp [(size_t)CC*CC];
__device__ unsigned char  g_w1 [(size_t)HID*CC];
__device__ unsigned char  g_w2 [(size_t)CC*HID];
// per-128-row-block nonzero flags for GEMM LHS skip
__device__ uint32_t       g_fh1[128];   // h after LN1  (qkv input)
__device__ uint32_t       g_fha[128];   // h after attn (proj input)
__device__ uint32_t       g_fh3[128];   // h after LN2  (fc1 input)
__device__ uint32_t       g_f4 [128];   // h4           (fc2 input)

__device__ __forceinline__ float sigmoidf_(float w){ return 1.f/(1.f+expf(-w)); }
__device__ __forceinline__ uint32_t smem_u32(const void* p){
    uint32_t a;
    asm("{ .reg .u64 t; cvta.to.shared.u64 t, %1; cvt.u32.u64 %0, t; }" : "=r"(a) : "l"(p));
    return a;
}
__device__ __forceinline__ uint32_t f2e4(float f){
    return (uint32_t)__nv_cvt_float_to_fp8(f, __NV_SATFINITE, __NV_E4M3);
}
#define FP8_ONE 0x38u

// ---------------- clear flags ----------------
__global__ void k_zero(uint32_t* f1, uint32_t* f2, uint32_t* f3, uint32_t* f4){
    int i = threadIdx.x;
    if (i < 128){ f1[i] = 0; f2[i] = 0; f3[i] = 0; f4[i] = 0; }
}

// ---------------- all weights -> e4m3, one kernel ----------------
__global__ void k_cvt_all(const float* __restrict__ a0, const float* __restrict__ a1,
                          const float* __restrict__ a2, const float* __restrict__ a3,
                          uint8_t* __restrict__ d0, uint8_t* __restrict__ d1,
                          uint8_t* __restrict__ d2, uint8_t* __restrict__ d3){
    int i = blockIdx.x*blockDim.x + threadIdx.x;   // float4 index
    const int n0 = 196608, n1 = 65536, n2 = 262144, n3 = 262144;
    const float* s; uint8_t* d; int off;
    if      (i < n0){            s=a0; d=d0; off=i; }
    else if (i < n0+n1){         s=a1; d=d1; off=i-n0; }
    else if (i < n0+n1+n2){      s=a2; d=d2; off=i-n0-n1; }
    else if (i < n0+n1+n2+n3){   s=a3; d=d3; off=i-n0-n1-n2; }
    else return;
    float4 v = ((const float4*)s)[off];
    uint32_t w = f2e4(v.x) | (f2e4(v.y)<<8) | (f2e4(v.z)<<16) | (f2e4(v.w)<<24);
    ((uint32_t*)d)[off] = w;
}

// ---------------- fused LIF(x) + depthwise 3x3 conv + residual ----------------
__global__ void __launch_bounds__(256) k_lifconv(
        const float* __restrict__ x, const float* __restrict__ lw,
        const float* __restrict__ cw, const float* __restrict__ cb,
        float* __restrict__ y){
    __shared__ unsigned char sp[4][256];
    int b = blockIdx.x >> 9, c = blockIdx.x & 511;
    int px = threadIdx.x;
    size_t base = ((size_t)b*512 + c)*256 + px;
    float decay = sigmoidf_(lw[0]);
    float xv[4];
#pragma unroll
    for (int t = 0; t < 4; t++) xv[t] = x[(size_t)t*PLANE + base];
    float v = 0.f;
#pragma unroll
    for (int t = 0; t < 4; t++){
        v += (xv[t] - v)*decay;
        unsigned char s = (v >= 1.f);
        sp[t][px] = s;
        if (s) v = 0.f;
    }
    __syncthreads();
    float wk[9];
#pragma unroll
    for (int j = 0; j < 9; j++) wk[j] = cw[c*9 + j];
    float bias = cb[c];
    int h = px >> 4, w = px & 15;
#pragma unroll
    for (int t = 0; t < 4; t++){
        float acc = bias;
#pragma unroll
        for (int dy = -1; dy <= 1; dy++){
            int hh = h + dy; if ((unsigned)hh >= 16u) continue;
#pragma unroll
            for (int dx = -1; dx <= 1; dx++){
                int ww = w + dx; if ((unsigned)ww >= 16u) continue;
                acc += wk[(dy+1)*3 + (dx+1)] * (float)sp[t][hh*16 + ww];
            }
        }
        y[(size_t)t*PLANE + base] = xv[t] + acc;
    }
}

// ---------------- transpose [tb][C][N] -> xt rows (bn*4+t) ----------------
__global__ void __launch_bounds__(256) k_tr(const float* __restrict__ y, float* __restrict__ xt){
    __shared__ float s[64][65];
    int bz = blockIdx.z;                 // t*16+b
    int t = bz >> 4, b = bz & 15;
    int n0 = blockIdx.x*64, c0 = blockIdx.y*64;
    int tid = threadIdx.x;
    const float* src = y + (size_t)bz*512*256;
#pragma unroll
    for (int it = 0; it < 4; it++){
        int cr = it*16 + (tid >> 4), ng = (tid & 15)*4;
        float4 f = *(const float4*)&src[(size_t)(c0+cr)*256 + n0 + ng];
        s[cr][ng+0] = f.x; s[cr][ng+1] = f.y; s[cr][ng+2] = f.z; s[cr][ng+3] = f.w;
    }
    __syncthreads();
#pragma unroll
    for (int it = 0; it < 4; it++){
        int nr = it*16 + (tid >> 4), cg = (tid & 15)*4;
        size_t row = (size_t)(b*256 + n0 + nr)*4 + t;
        float4 f = make_float4(s[cg][nr], s[cg+1][nr], s[cg+2][nr], s[cg+3][nr]);
        *(float4*)&xt[row*512 + c0 + cg] = f;
    }
}

// ---------------- LayerNorm(C) + LIF over T -> e4m3 spikes (+flags) ----------------
__global__ void __launch_bounds__(128) k_ln_lif(
        const float* __restrict__ xt, const float* __restrict__ g, const float* __restrict__ bv,
        const float* __restrict__ lw, int lwi, uint8_t* __restrict__ h,
        uint32_t* __restrict__ flag){
    int bn = blockIdx.x, tid = threadIdx.x;
    int lane = tid & 31, w = tid >> 5;
    __shared__ float sw_[4][4], sq_[4][4];
    float decay = sigmoidf_(lw[lwi]);
    float4 gg = *(const float4*)&g[tid*4];
    float4 bb = *(const float4*)&bv[tid*4];
    float4 xv[4];
#pragma unroll
    for (int t = 0; t < 4; t++)
        xv[t] = *(const float4*)&xt[((size_t)bn*4 + t)*512 + tid*4];
    float v0=0,v1=0,v2=0,v3=0;
    bool any = false;
#pragma unroll
    for (int t = 0; t < 4; t++){
        float4 xw = xv[t];
        float s = xw.x+xw.y+xw.z+xw.w;
        float q = xw.x*xw.x+xw.y*xw.y+xw.z*xw.z+xw.w*xw.w;
#pragma unroll
        for (int o = 16; o > 0; o >>= 1){
            s += __shfl_xor_sync(0xffffffffu, s, o);
            q += __shfl_xor_sync(0xffffffffu, q, o);
        }
        if (lane == 0){ sw_[t][w] = s; sq_[t][w] = q; }
        __syncthreads();
        float ts = sw_[t][0]+sw_[t][1]+sw_[t][2]+sw_[t][3];
        float tq = sq_[t][0]+sq_[t][1]+sq_[t][2]+sq_[t][3];
        float mean = ts*(1.f/512.f);
        float var  = tq*(1.f/512.f) - mean*mean;
        float rstd = rsqrtf(var + 1e-5f);
        float y0 = (xw.x-mean)*rstd*gg.x + bb.x;
        float y1 = (xw.y-mean)*rstd*gg.y + bb.y;
        float y2 = (xw.z-mean)*rstd*gg.z + bb.z;
        float y3 = (xw.w-mean)*rstd*gg.w + bb.w;
        v0 += (y0-v0)*decay; v1 += (y1-v1)*decay; v2 += (y2-v2)*decay; v3 += (y3-v3)*decay;
        bool s0 = v0>=1.f, s1 = v1>=1.f, s2 = v2>=1.f, s3 = v3>=1.f;
        any |= (s0|s1|s2|s3);
        uint32_t pw = (s0?FP8_ONE:0u) | ((s1?FP8_ONE:0u)<<8)
                    | ((s2?FP8_ONE:0u)<<16) | ((s3?FP8_ONE:0u)<<24);
        ((uint32_t*)(h + ((size_t)bn*4 + t)*512))[tid] = pw;
        if (s0) v0=0.f; if (s1) v1=0.f; if (s2) v2=0.f; if (s3) v3=0.f;
        __syncthreads();
    }
    uint32_t m = __ballot_sync(0xffffffffu, any);
    if (lane == 0 && m) atomicOr(&flag[bn >> 5], 1u);
}

// ---------------- FP8 GEMM with zero-block skip ----------------
// EP: 0 = QKV (LIF -> bit masks), 1 = proj (xt += acc+bias),
//     2 = fc1 (LIF+bias -> h4 e4m3, sets out-flags), 3 = fc2 (out = xt+acc+bias, transposed)
#define BMT 128
#define BNT 128
#define BKB 64
#define STG 3
#define ROWB 80
#define STAGE_BYTES (2*BMT*ROWB)
#define GEMM_DSMEM (STG*STAGE_BYTES)

template<int EP>
__global__ void __launch_bounds__(256, 2) k_gemm(
        const uint8_t* __restrict__ A, const uint8_t* __restrict__ W,
        int N, int K,
        const float* __restrict__ lw, const float* __restrict__ bias,
        float* __restrict__ xt, float* __restrict__ out,
        uint32_t* __restrict__ qm, uint32_t* __restrict__ km, uint32_t* __restrict__ vm,
        uint8_t* __restrict__ h4,
        const uint32_t* __restrict__ nzf, uint32_t* __restrict__ outflag){
    extern __shared__ char dsm[];
    const int tid  = threadIdx.x;
    const int lane = tid & 31, warp = tid >> 5;
    const int wm = warp >> 1, wn = warp & 1;
    const int bm = blockIdx.y*BMT, bn = blockIdx.x*BNT;
    const uint32_t sbase = smem_u32(dsm);
    const int nk = K >> 6;

    float acc[2][8][4];
#pragma unroll
    for (int i = 0; i < 2; i++)
#pragma unroll
        for (int j = 0; j < 8; j++)
#pragma unroll
            for (int r = 0; r < 4; r++) acc[i][j][r] = 0.f;

    const bool live = (nzf == nullptr) || (nzf[blockIdx.y] != 0);

    if (live){
        auto load_stage = [&](int j){
            int s = j % STG;
            uint32_t sa = sbase + s*STAGE_BYTES;
            uint32_t sb = sa + BMT*ROWB;
            int k0 = j*BKB;
#pragma unroll
            for (int i = 0; i < 2; i++){
                int ch  = i*256 + tid;
                int row = ch >> 2, colb = (ch & 3)*16;
                const char* ga = (const char*)(A + (size_t)(bm+row)*K + k0 + colb);
                const char* gb = (const char*)(W + (size_t)(bn+row)*K + k0 + colb);
                uint32_t da = sa + (uint32_t)(row*ROWB + colb);
                uint32_t db = sb + (uint32_t)(row*ROWB + colb);
                asm volatile("cp.async.cg.shared.global [%0], [%1], 16;" :: "r"(da), "l"(ga));
                asm volatile("cp.async.cg.shared.global [%0], [%1], 16;" :: "r"(db), "l"(gb));
            }
            asm volatile("cp.async.commit_group;");
        };

        load_stage(0);
        if (nk > 1) load_stage(1); else asm volatile("cp.async.commit_group;");

        for (int j = 0; j < nk; j++){
            asm volatile("cp.async.wait_group 1;");
            __syncthreads();
            int s = j % STG;
            uint32_t abase = sbase + s*STAGE_BYTES;
            uint32_t bbase = abase + BMT*ROWB;
#pragma unroll
            for (int ks = 0; ks < 2; ks++){
                uint32_t a[2][4], b[4][4];
#pragma unroll
                for (int mt = 0; mt < 2; mt++){
                    int row = wm*32 + mt*16 + (lane & 15);
                    int colb = ks*32 + ((lane >> 4) << 4);
                    uint32_t ad = abase + (uint32_t)(row*ROWB + colb);
                    asm volatile("ldmatrix.sync.aligned.m8n8.x4.shared.b16 {%0,%1,%2,%3}, [%4];"
                                 : "=r"(a[mt][0]), "=r"(a[mt][1]), "=r"(a[mt][2]), "=r"(a[mt][3])
                                 : "r"(ad));
                }
#pragma unroll
                for (int ng = 0; ng < 4; ng++){
                    int n = wn*64 + ng*16 + (lane & 7) + (((lane >> 4) & 1) << 3);
                    int colb = ks*32 + (((lane >> 3) & 1) << 4);
                    uint32_t bd = bbase + (uint32_t)(n*ROWB + colb);
                    asm volatile("ldmatrix.sync.aligned.m8n8.x4.shared.b16 {%0,%1,%2,%3}, [%4];"
                                 : "=r"(b[ng][0]), "=r"(b[ng][1]), "=r"(b[ng][2]), "=r"(b[ng][3])
                                 : "r"(bd));
                }
#pragma unroll
                for (int mt = 0; mt < 2; mt++)
#pragma unroll
                    for (int nf = 0; nf < 8; nf++){
                        uint32_t b0 = b[nf >> 1][(nf & 1)*2];
                        uint32_t b1 = b[nf >> 1][(nf & 1)*2 + 1];
                        asm volatile(
                            "mma.sync.aligned.m16n8k32.row.col.f32.e4m3.e4m3.f32 "
                            "{%0,%1,%2,%3}, {%4,%5,%6,%7}, {%8,%9}, {%0,%1,%2,%3};"
                            : "+f"(acc[mt][nf][0]), "+f"(acc[mt][nf][1]),
                              "+f"(acc[mt][nf][2]), "+f"(acc[mt][nf][3])
                            : "r"(a[mt][0]), "r"(a[mt][1]), "r"(a[mt][2]), "r"(a[mt][3]),
                              "r"(b0), "r"(b1));
                    }
            }
            if (j + 2 < nk) load_stage(j + 2);
            else            asm volatile("cp.async.commit_group;");
            __syncthreads();
        }
        asm volatile("cp.async.wait_group 0;");
    }

    // ================= epilogues =================
    if (EP == 1){
#pragma unroll
        for (int mt = 0; mt < 2; mt++){
            int r0 = bm + wm*32 + mt*16 + (lane >> 2);
#pragma unroll
            for (int nf = 0; nf < 8; nf++){
                int col = bn + wn*64 + nf*8 + (lane & 3)*2;
                float2 bb = *(const float2*)&bias[col];
                float2* p0 = (float2*)&xt[(size_t)r0*512 + col];
                float2 q0 = *p0;
                q0.x += acc[mt][nf][0] + bb.x; q0.y += acc[mt][nf][1] + bb.y;
                *p0 = q0;
                float2* p1 = (float2*)&xt[(size_t)(r0+8)*512 + col];
                float2 q1 = *p1;
                q1.x += acc[mt][nf][2] + bb.x; q1.y += acc[mt][nf][3] + bb.y;
                *p1 = q1;
            }
        }
        return;
    }

    if (EP == 3){
#pragma unroll
        for (int mt = 0; mt < 2; mt++){
            int r0 = bm + wm*32 + mt*16 + (lane >> 2);
#pragma unroll
            for (int nf = 0; nf < 8; nf++){
                int col = bn + wn*64 + nf*8 + (lane & 3)*2;
                float2 bb = *(const float2*)&bias[col];
                float2 x0 = *(const float2*)&xt[(size_t)r0*512 + col];
                float2 x1 = *(const float2*)&xt[(size_t)(r0+8)*512 + col];
                acc[mt][nf][0] += x0.x + bb.x; acc[mt][nf][1] += x0.y + bb.y;
                acc[mt][nf][2] += x1.x + bb.x; acc[mt][nf][3] += x1.y + bb.y;
            }
        }
    }

    bool anyep2 = false;
    float* es = (float*)dsm;
    for (int cc = 0; cc < 4; cc++){
        __syncthreads();
        if (wn == (cc >> 1)){
            int nfb = (cc & 1)*4;
#pragma unroll
            for (int mt = 0; mt < 2; mt++)
#pragma unroll
                for (int f = 0; f < 4; f++){
                    int nf = nfb + f;
                    int lc = f*8 + (lane & 3)*2;
                    int r0 = wm*32 + mt*16 + (lane >> 2);
                    es[r0*33 + lc]     = acc[mt][nf][0];
                    es[r0*33 + lc + 1] = acc[mt][nf][1];
                    es[(r0+8)*33 + lc]     = acc[mt][nf][2];
                    es[(r0+8)*33 + lc + 1] = acc[mt][nf][3];
                }
        }
        __syncthreads();
        int col0 = bn + cc*32;
        if (EP == 0){
            int isel = col0 >> 9, hh = (col0 >> 6) & 7, gsel = (col0 >> 5) & 1;
            float decay = sigmoidf_(lw[2 + isel]);
            uint32_t* mdst = (isel == 0) ? qm : (isel == 1) ? km : vm;
#pragma unroll
            for (int k2 = 0; k2 < 4; k2++){
                int j = k2*8 + warp;
                int tok = (bm >> 2) + j;
                int b = tok >> 8, n = tok & 255;
                float v = 0.f;
#pragma unroll
                for (int t = 0; t < 4; t++){
                    float val = es[(4*j + t)*33 + lane];
                    v += (val - v)*decay;
                    bool s = v >= 1.f;
                    uint32_t m = __ballot_sync(0xffffffffu, s);
                    if (s) v = 0.f;
                    if (lane == 0)
                        mdst[(((size_t)((t*16 + b)*8 + hh)*256 + n))*2 + gsel] = m;
                }
            }
        } else if (EP == 2){
            float decay = sigmoidf_(lw[7]);
#pragma unroll
            for (int k2 = 0; k2 < 4; k2++){
                int idx = k2*256 + tid;
                int j = idx >> 5, c = idx & 31;
                int col = col0 + c;
                float bvv = bias[col];
                int rb = bm + 4*j;
                float v = 0.f;
#pragma unroll
                for (int t = 0; t < 4; t++){
                    float val = es[(4*j + t)*33 + c] + bvv;
                    v += (val - v)*decay;
                    bool s = v >= 1.f;
                    anyep2 |= s;
                    h4[(size_t)(rb + t)*N + col] = s ? (uint8_t)FP8_ONE : (uint8_t)0;
                    if (s) v = 0.f;
                }
            }
        } else { // EP == 3
            int u = tid >> 1, half = tid & 1;
            int t = u >> 5, c = u & 31;
            int col = col0 + c;
            int tokb = bm >> 2;
            int b = tokb >> 8, n00 = (tokb & 255) + half*16;
            float* op = out + (((size_t)(t*16 + b)*512 + col)*256 + n00);
#pragma unroll
            for (int q4 = 0; q4 < 4; q4++){
                float4 vv;
                vv.x = es[(4*(half*16 + q4*4 + 0) + t)*33 + c];
                vv.y = es[(4*(half*16 + q4*4 + 1) + t)*33 + c];
                vv.z = es[(4*(half*16 + q4*4 + 2) + t)*33 + c];
                vv.w = es[(4*(half*16 + q4*4 + 3) + t)*33 + c];
                *(float4*)(op + q4*4) = vv;
            }
        }
    }
    if (EP == 2){
        uint32_t m = __ballot_sync(0xffffffffu, anyep2);
        if (lane == 0 && m) atomicOr(&outflag[blockIdx.y], 1u);
    }
}

// ---------------- kv = k^T v from bit masks ----------------
__global__ void __launch_bounds__(256) k_kv(const uint32_t* __restrict__ km,
                                            const uint32_t* __restrict__ vm,
                                            float* __restrict__ kvout){
    __shared__ uint32_t mk[256][2], mv[256][2];
    __shared__ uint32_t kb[64][8], vb[64][8];
    int tbh = blockIdx.x;
    int tid = threadIdx.x, lane = tid & 31, w = tid >> 5;
    uint2 a = ((const uint2*)km)[(size_t)tbh*256 + tid];
    uint2 c = ((const uint2*)vm)[(size_t)tbh*256 + tid];
    mk[tid][0] = a.x; mk[tid][1] = a.y;
    mv[tid][0] = c.x; mv[tid][1] = c.y;
    __syncthreads();
    uint32_t k0 = mk[w*32+lane][0], k1 = mk[w*32+lane][1];
    uint32_t v0 = mv[w*32+lane][0], v1 = mv[w*32+lane][1];
#pragma unroll
    for (int db = 0; db < 32; db++){
        uint32_t m;
        m = __ballot_sync(0xffffffffu, (k0 >> db) & 1); if (lane == 0) kb[db][w] = m;
        m = __ballot_sync(0xffffffffu, (k1 >> db) & 1); if (lane == 0) kb[32+db][w] = m;
        m = __ballot_sync(0xffffffffu, (v0 >> db) & 1); if (lane == 0) vb[db][w] = m;
        m = __ballot_sync(0xffffffffu, (v1 >> db) & 1); if (lane == 0) vb[32+db][w] = m;
    }
    __syncthreads();
    for (int o = tid; o < DH*DH; o += 256){
        int d = o >> 6, e = o & 63;
        int cnt = 0;
#pragma unroll
        for (int g = 0; g < 8; g++) cnt += __popc(kb[d][g] & vb[e][g]);
        kvout[(size_t)tbh*DH*DH + o] = (float)cnt;
    }
}

// ---------------- attention a = q@kv*scale + LIF -> e4m3 spikes (+flags) ----------------
__global__ void __launch_bounds__(256) k_attn_lif(const uint32_t* __restrict__ qm,
                                                  const float* __restrict__ kvin,
                                                  const float* __restrict__ lw,
                                                  uint8_t* __restrict__ h,
                                                  uint32_t* __restrict__ flag){
    __shared__ float skv[64][17];
    int bx = blockIdx.x;               // b*8 + h
    int b = bx >> 3, hh = bx & 7;
    int n = threadIdx.x;
    int lane = n & 31;
    uint32_t mq[4][2];
#pragma unroll
    for (int t = 0; t < 4; t++){
        uint2 a = ((const uint2*)qm)[(size_t)((t*16+b)*8+hh)*256 + n];
        mq[t][0] = a.x; mq[t][1] = a.y;
    }
    float decay = sigmoidf_(lw[5]);
    size_t hbase = ((size_t)(b*256 + n)*4)*512 + hh*64;
    bool any = false;
    for (int eg = 0; eg < 4; eg++){
        float v[16];
#pragma unroll
        for (int e = 0; e < 16; e++) v[e] = 0.f;
        for (int t = 0; t < 4; t++){
            int tbh = (t*16 + b)*8 + hh;
            __syncthreads();
            { int d = n >> 2, io = (n & 3)*4;
              float4 f = *(const float4*)&kvin[(size_t)tbh*4096 + d*64 + eg*16 + io];
              skv[d][io] = f.x; skv[d][io+1] = f.y; skv[d][io+2] = f.z; skv[d][io+3] = f.w; }
            __syncthreads();
            float acc[16];
#pragma unroll
            for (int e = 0; e < 16; e++) acc[e] = 0.f;
#pragma unroll
            for (int g = 0; g < 2; g++){
                uint32_t m = mq[t][g];
                for (int db = 0; db < 32; db++){
                    if ((m >> db) & 1){
                        int d = g*32 + db;
#pragma unroll
                        for (int e = 0; e < 16; e++) acc[e] += skv[d][e];
                    }
                }
            }
            uint32_t pw[4];
#pragma unroll
            for (int qq = 0; qq < 4; qq++){
                uint32_t wv = 0;
#pragma unroll
                for (int e2 = 0; e2 < 4; e2++){
                    int e = qq*4 + e2;
                    float a0 = acc[e]*0.125f;
                    v[e] += (a0 - v[e])*decay;
                    bool s = v[e] >= 1.f;
                    any |= s;
                    wv |= (s ? FP8_ONE : 0u) << (e2*8);
                    if (s) v[e] = 0.f;
                }
                pw[qq] = wv;
            }
            *(uint4*)(h + hbase + (size_t)t*512 + eg*16) = make_uint4(pw[0],pw[1],pw[2],pw[3]);
        }
    }
    uint32_t m = __ballot_sync(0xffffffffu, any);
    if (lane == 0 && m) atomicOr(&flag[(b*256 + n) >> 5], 1u);
}

// ---------------- launch ----------------
extern "C" void kernel_launch(void* const* d_in, const int* in_sizes, int n_in,
                              void* d_out, int out_size){
    const float* x      = (const float*)d_in[0];
    const float* conv_w = (const float*)d_in[1];
    const float* conv_b = (const float*)d_in[2];
    const float* ln1_g  = (const float*)d_in[3];
    const float* ln1_b  = (const float*)d_in[4];
    const float* qkv_w  = (const float*)d_in[5];
    const float* proj_w = (const float*)d_in[6];
    const float* proj_b = (const float*)d_in[7];
    const float* ln2_g  = (const float*)d_in[8];
    const float* ln2_b  = (const float*)d_in[9];
    const float* fc1_w  = (const float*)d_in[10];
    const float* fc1_b  = (const float*)d_in[11];
    const float* fc2_w  = (const float*)d_in[12];
    const float* fc2_b  = (const float*)d_in[13];
    const float* lif_w  = (const float*)d_in[14];
    float* out = (float*)d_out;

    void *p_xt, *p_y, *p_kv, *p_h, *p_h4, *p_qm, *p_km, *p_vm,
         *p_wq, *p_wp, *p_w1, *p_w2, *p_f1, *p_fa, *p_f3, *p_f4;
    cudaGetSymbolAddress(&p_xt, g_xt);
    cudaGetSymbolAddress(&p_y,  g_y);
    cudaGetSymbolAddress(&p_kv, g_kv);
    cudaGetSymbolAddress(&p_h,  g_h);
    cudaGetSymbolAddress(&p_h4, g_h4);
    cudaGetSymbolAddress(&p_qm, g_qm);
    cudaGetSymbolAddress(&p_km, g_km);
    cudaGetSymbolAddress(&p_vm, g_vm);
    cudaGetSymbolAddress(&p_wq, g_wq);
    cudaGetSymbolAddress(&p_wp, g_wp);
    cudaGetSymbolAddress(&p_w1, g_w1);
    cudaGetSymbolAddress(&p_w2, g_w2);
    cudaGetSymbolAddress(&p_f1, g_fh1);
    cudaGetSymbolAddress(&p_fa, g_fha);
    cudaGetSymbolAddress(&p_f3, g_fh3);
    cudaGetSymbolAddress(&p_f4, g_f4);

    float* xt = (float*)p_xt;
    float* y  = (float*)p_y;
    float* kv = (float*)p_kv;
    uint8_t* h  = (uint8_t*)p_h;
    uint8_t* h4 = (uint8_t*)p_h4;
    uint32_t* qm = (uint32_t*)p_qm;
    uint32_t* km = (uint32_t*)p_km;
    uint32_t* vm = (uint32_t*)p_vm;
    uint8_t* wq = (uint8_t*)p_wq;
    uint8_t* wp = (uint8_t*)p_wp;
    uint8_t* w1 = (uint8_t*)p_w1;
    uint8_t* w2 = (uint8_t*)p_w2;
    uint32_t* f1 = (uint32_t*)p_f1;
    uint32_t* fa = (uint32_t*)p_fa;
    uint32_t* f3 = (uint32_t*)p_f3;
    uint32_t* f4 = (uint32_t*)p_f4;

    cudaFuncSetAttribute(k_gemm<0>, cudaFuncAttributeMaxDynamicSharedMemorySize, GEMM_DSMEM);
    cudaFuncSetAttribute(k_gemm<1>, cudaFuncAttributeMaxDynamicSharedMemorySize, GEMM_DSMEM);
    cudaFuncSetAttribute(k_gemm<2>, cudaFuncAttributeMaxDynamicSharedMemorySize, GEMM_DSMEM);
    cudaFuncSetAttribute(k_gemm<3>, cudaFuncAttributeMaxDynamicSharedMemorySize, GEMM_DSMEM);

    // 0) clear flags
    k_zero<<<1, 128>>>(f1, fa, f3, f4);
    // 1) weights -> e4m3
    k_cvt_all<<<3072, 256>>>(qkv_w, proj_w, fc1_w, fc2_w, wq, wp, w1, w2);
    // 2) fused LIF(x) + conv + residual -> y
    k_lifconv<<<BB*CC, 256>>>(x, lif_w, conv_w, conv_b, y);
    // 3) transpose -> xt rows (bn*4+t)
    k_tr<<<dim3(4, 8, 64), 256>>>(y, xt);
    // 4) LN1 + LIF -> h (+f1)
    k_ln_lif<<<BNROWS, 128>>>(xt, ln1_g, ln1_b, lif_w, 1, h, f1);
    // 5) QKV GEMM + LIF -> bit masks
    k_gemm<0><<<dim3(12, 128), 256, GEMM_DSMEM>>>(h, wq, 3*CC, CC, lif_w, nullptr,
                                                  nullptr, nullptr, qm, km, vm, nullptr, f1, nullptr);
    // 6) kv = k^T v
    k_kv<<<TT*BB*NHEAD, 256>>>(km, vm, kv);
    // 7) a = q@kv*scale + LIF -> h (+fa)
    k_attn_lif<<<BB*NHEAD, 256>>>(qm, kv, lif_w, h, fa);
    // 8) proj GEMM: xt += h@Wp^T + proj_b (skips zero blocks)
    k_gemm<1><<<dim3(4, 128), 256, GEMM_DSMEM>>>(h, wp, CC, CC, lif_w, proj_b,
                                                 xt, nullptr, nullptr, nullptr, nullptr, nullptr, fa, nullptr);
    // 9) LN2 + LIF -> h (+f3)
    k_ln_lif<<<BNROWS, 128>>>(xt, ln2_g, ln2_b, lif_w, 6, h, f3);
    // 10) FC1 GEMM + bias + LIF -> h4 (+f4)
    k_gemm<2><<<dim3(16, 128), 256, GEMM_DSMEM>>>(h, w1, HID, CC, lif_w, fc1_b,
                                                  nullptr, nullptr, nullptr, nullptr, nullptr, h4, f3, f4);
    // 11) FC2 GEMM + bias + residual, transposed -> out (skips zero blocks)
    k_gemm<3><<<dim3(4, 128), 256, GEMM_DSMEM>>>(h4, w2, CC, HID, lif_w, fc2_b,
                                                 xt, out, nullptr, nullptr, nullptr, nullptr, f4, nullptr);
}